// round 13
// baseline (speedup 1.0000x reference)
#include <cuda_runtime.h>
#include <cuda_fp16.h>
#include <math.h>
#include <stdint.h>

#define NTOK 4096
#define DIM  1024
#define NE   8
#define HH   4096
#define CAP  1280
#define NK   (NTOK*2)

// GEMM tiling: warp 64x32, BK=64, 3-stage single-sync; all-fp16 operands
#define BK      64
#define STRD    72                    // smem row stride in fp16 elems (144 B, conflict-free)
#define TILEB   (128*STRD*2)          // 18432 B per tile (128 rows)
#define STAGEB  (2*TILEB)             // A, B = 36864 B
#define SMEM_DYN (3*STAGEB)           // 110592 B, 3 stages; 2 CTA/SM

// ---------------- scratch (device globals; no allocations) ----------------
__device__ int   g_e0[NTOK], g_e1[NTOK];
__device__ float g_g0[NTOK], g_g1[NTOK];
__device__ int   g_item_e[NK];
__device__ int   g_item_pos[NK];
__device__ unsigned char g_item_keep[NK];
__device__ float g_item_w[NK];
__device__ int   g_slot_token[NE*CAP];
__device__ int   g_load[NE];
__device__ float g_pimp[512*NE];
__device__ float g_pz[512];

__device__ unsigned short g_xn[(size_t)NE*CAP*DIM];     // fp16
__device__ unsigned short g_w1[(size_t)NE*2*HH*DIM];    // fp16, transposed [e][n][k]
__device__ unsigned short g_w2[(size_t)NE*DIM*HH];      // fp16, transposed [e][n][k]
__device__ unsigned short g_v[(size_t)NE*CAP*HH];       // fp16
__device__ float g_eo[(size_t)NE*CAP*DIM];

// ---------------- helpers ----------------
__device__ __forceinline__ uint32_t smem_u32(const void* p) {
    uint32_t a;
    asm("{ .reg .u64 t; cvta.to.shared.u64 t, %1; cvt.u32.u64 %0, t; }" : "=r"(a) : "l"(p));
    return a;
}
__device__ __forceinline__ void cpa16(uint32_t dst, const void* src) {
    asm volatile("cp.async.ca.shared.global [%0], [%1], 16;" :: "r"(dst), "l"(src));
}
#define CP_COMMIT() asm volatile("cp.async.commit_group;" ::: "memory")
#define CP_WAIT(n)  asm volatile("cp.async.wait_group %0;" :: "n"(n) : "memory")

__device__ __forceinline__ void ldm4(uint32_t* r, uint32_t a) {
    asm volatile("ldmatrix.sync.aligned.m8n8.x4.shared.b16 {%0,%1,%2,%3}, [%4];"
        : "=r"(r[0]), "=r"(r[1]), "=r"(r[2]), "=r"(r[3]) : "r"(a));
}
__device__ __forceinline__ void mma16816(float* d, const uint32_t* a, const uint32_t* b0) {
    asm volatile("mma.sync.aligned.m16n8k16.row.col.f32.f16.f16.f32 "
        "{%0,%1,%2,%3}, {%4,%5,%6,%7}, {%8,%9}, {%0,%1,%2,%3};"
        : "+f"(d[0]), "+f"(d[1]), "+f"(d[2]), "+f"(d[3])
        : "r"(a[0]), "r"(a[1]), "r"(a[2]), "r"(a[3]), "r"(b0[0]), "r"(b0[1]));
}
__device__ __forceinline__ unsigned short f2h(float x) {
    __half hh = __float2half_rn(x);
    return *reinterpret_cast<unsigned short*>(&hh);
}

// ---------------- weight transpose + fp16: 64x64 tiles, packed writes -------
__global__ void k_tw1(const float* __restrict__ W) {
    __shared__ float tile[64][65];
    int e = blockIdx.z;
    int n0 = blockIdx.x * 64, k0 = blockIdx.y * 64;
    const float* S = W + (size_t)e * DIM * (2*HH);
    int tx = threadIdx.x, ty = threadIdx.y;
#pragma unroll
    for (int i = 0; i < 8; i++) {
        int kl = ty + i*8;
        const float* row = S + (size_t)(k0 + kl) * (2*HH) + n0;
        tile[kl][tx]      = row[tx];
        tile[kl][tx + 32] = row[tx + 32];
    }
    __syncthreads();
    size_t ob = (size_t)e * (2*HH) * DIM;
#pragma unroll
    for (int i = 0; i < 8; i++) {
        int nl = ty + i*8;
        unsigned short h0 = f2h(tile[tx*2][nl]);
        unsigned short h1 = f2h(tile[tx*2 + 1][nl]);
        size_t o = ob + (size_t)(n0 + nl) * DIM + k0;
        ((uint32_t*)(g_w1 + o))[tx] = (uint32_t)h0 | ((uint32_t)h1 << 16);
    }
}
__global__ void k_tw2(const float* __restrict__ W) {
    __shared__ float tile[64][65];
    int e = blockIdx.z;
    int n0 = blockIdx.x * 64, k0 = blockIdx.y * 64;
    const float* S = W + (size_t)e * HH * DIM;
    int tx = threadIdx.x, ty = threadIdx.y;
#pragma unroll
    for (int i = 0; i < 8; i++) {
        int kl = ty + i*8;
        const float* row = S + (size_t)(k0 + kl) * DIM + n0;
        tile[kl][tx]      = row[tx];
        tile[kl][tx + 32] = row[tx + 32];
    }
    __syncthreads();
    size_t ob = (size_t)e * DIM * HH;
#pragma unroll
    for (int i = 0; i < 8; i++) {
        int nl = ty + i*8;
        unsigned short h0 = f2h(tile[tx*2][nl]);
        unsigned short h1 = f2h(tile[tx*2 + 1][nl]);
        size_t o = ob + (size_t)(n0 + nl) * HH + k0;
        ((uint32_t*)(g_w2 + o))[tx] = (uint32_t)h0 | ((uint32_t)h1 << 16);
    }
}

// ---------------- router + fused stats ----------------
__global__ void k_router(const float* __restrict__ x, const float* __restrict__ Wr,
                         const float* __restrict__ br) {
    int warp = threadIdx.x >> 5, lane = threadIdx.x & 31;
    int n = blockIdx.x * 8 + warp;
    float acc[8];
#pragma unroll
    for (int j = 0; j < 8; j++) acc[j] = 0.f;
    const float* xr = x + (size_t)n * DIM;
    for (int d = lane; d < DIM; d += 32) {
        float xv = xr[d];
        float4 w0 = *(const float4*)(Wr + (size_t)d * 8);
        float4 w1 = *(const float4*)(Wr + (size_t)d * 8 + 4);
        acc[0] += xv * w0.x; acc[1] += xv * w0.y; acc[2] += xv * w0.z; acc[3] += xv * w0.w;
        acc[4] += xv * w1.x; acc[5] += xv * w1.y; acc[6] += xv * w1.z; acc[7] += xv * w1.w;
    }
#pragma unroll
    for (int off = 16; off; off >>= 1)
#pragma unroll
        for (int j = 0; j < 8; j++) acc[j] += __shfl_down_sync(0xffffffffu, acc[j], off);
    __shared__ float simp[8][8];
    __shared__ float simz[8];
    if (lane == 0) {
        float lg[8];
#pragma unroll
        for (int j = 0; j < 8; j++) lg[j] = acc[j] + br[j];
        int b0 = 0;
#pragma unroll
        for (int j = 1; j < 8; j++) if (lg[j] > lg[b0]) b0 = j;
        int b1 = (b0 == 0) ? 1 : 0;
#pragma unroll
        for (int j = 0; j < 8; j++) if (j != b0 && lg[j] > lg[b1]) b1 = j;
        g_e0[n] = b0; g_e1[n] = b1;
        float gg = 1.f / (1.f + expf(lg[b1] - lg[b0]));
        g_g0[n] = gg; g_g1[n] = 1.f - gg;
        float m = lg[0];
#pragma unroll
        for (int j = 1; j < 8; j++) m = fmaxf(m, lg[j]);
        float p[8], s = 0.f, zs = 0.f;
#pragma unroll
        for (int j = 0; j < 8; j++) { p[j] = expf(lg[j] - m); s += p[j]; zs += lg[j]*lg[j]; }
#pragma unroll
        for (int j = 0; j < 8; j++) simp[warp][j] = p[j] / s;
        simz[warp] = zs;
    }
    __syncthreads();
    if (threadIdx.x < 8) {
        float tsum = 0.f;
#pragma unroll
        for (int w2 = 0; w2 < 8; w2++) tsum += simp[w2][threadIdx.x];
        g_pimp[blockIdx.x*8 + threadIdx.x] = tsum;
    } else if (threadIdx.x == 8) {
        float tz = 0.f;
#pragma unroll
        for (int w2 = 0; w2 < 8; w2++) tz += simz[w2];
        g_pz[blockIdx.x] = tz;
    }
}

// ---------------- slot assignment ----------------
__global__ void k_assign() {
    __shared__ int scnt[256][NE];
    int t = threadIdx.x;
    int cnt[NE];
#pragma unroll
    for (int e = 0; e < NE; e++) cnt[e] = 0;
    int i0 = t * 32;
    for (int j = 0; j < 32; j++) {
        int i = i0 + j;
        int e = (i < NTOK) ? g_e0[i] : g_e1[i - NTOK];
        cnt[e]++;
    }
#pragma unroll
    for (int e = 0; e < NE; e++) scnt[t][e] = cnt[e];
    __syncthreads();
    if (t < NE) {
        int run = 0;
        for (int j = 0; j < 256; j++) { int tmp = scnt[j][t]; scnt[j][t] = run; run += tmp; }
        g_load[t] = (run < CAP) ? run : CAP;
    }
    __syncthreads();
    int off[NE];
#pragma unroll
    for (int e = 0; e < NE; e++) off[e] = scnt[t][e];
    for (int j = 0; j < 32; j++) {
        int i = i0 + j;
        int nn = (i < NTOK) ? i : (i - NTOK);
        int e  = (i < NTOK) ? g_e0[i] : g_e1[i - NTOK];
        int pos = off[e]++;
        int keep = (pos < CAP);
        g_item_e[i] = e;
        g_item_pos[i] = keep ? pos : (CAP - 1);
        g_item_keep[i] = (unsigned char)keep;
        if (keep) g_slot_token[e*CAP + pos] = nn;
    }
    __syncthreads();
    for (int n = t; n < NTOK; n += 256) {
        float kg0 = g_item_keep[n]        ? g_g0[n] : 0.f;
        float kg1 = g_item_keep[NTOK + n] ? g_g1[n] : 0.f;
        float denom = fmaxf(kg0 + kg1, 1e-8f);
        g_item_w[n] = kg0 / denom;
        g_item_w[NTOK + n] = kg1 / denom;
    }
}

// ---------------- gather + LayerNorm -> fp16 xn ----------------
__global__ void k_ln(const float* __restrict__ x, const float* __restrict__ lns,
                     const float* __restrict__ lnb) {
    int slot = blockIdx.x;
    int e = slot / CAP, c = slot % CAP;
    if (c >= g_load[e]) return;
    int token = g_slot_token[slot];
    int t = threadIdx.x;
    float4 xv = *(const float4*)(x + (size_t)token*DIM + t*4);
    float s = xv.x + xv.y + xv.z + xv.w;
    float q = xv.x*xv.x + xv.y*xv.y + xv.z*xv.z + xv.w*xv.w;
#pragma unroll
    for (int off = 16; off; off >>= 1) {
        s += __shfl_down_sync(0xffffffffu, s, off);
        q += __shfl_down_sync(0xffffffffu, q, off);
    }
    __shared__ float ws[8], wq[8];
    __shared__ float s_mu, s_rstd;
    int warp = t >> 5, lane = t & 31;
    if (lane == 0) { ws[warp] = s; wq[warp] = q; }
    __syncthreads();
    if (t == 0) {
        float S = 0.f, Q = 0.f;
#pragma unroll
        for (int w = 0; w < 8; w++) { S += ws[w]; Q += wq[w]; }
        float mu = S / DIM;
        float var = Q / DIM - mu*mu;
        s_mu = mu; s_rstd = rsqrtf(var + 1e-5f);
    }
    __syncthreads();
    float mu = s_mu, r = s_rstd;
    float4 sc = *(const float4*)(lns + (size_t)e*DIM + t*4);
    float4 bi = *(const float4*)(lnb + (size_t)e*DIM + t*4);
    unsigned short h[4];
    h[0] = f2h((xv.x - mu)*r*sc.x + bi.x);
    h[1] = f2h((xv.y - mu)*r*sc.y + bi.y);
    h[2] = f2h((xv.z - mu)*r*sc.z + bi.z);
    h[3] = f2h((xv.w - mu)*r*sc.w + bi.w);
    uint2 ph;
    ph.x = (uint32_t)h[0] | ((uint32_t)h[1] << 16);
    ph.y = (uint32_t)h[2] | ((uint32_t)h[3] << 16);
    *(uint2*)(g_xn + (size_t)slot*DIM + t*4) = ph;
}

// =======================================================================
// fp16 warp-MMA core: warp tile 64x32, BK=64, 3-stage single-sync.
// smem stage: A [128][STRD], B [128][STRD].
// =======================================================================
__device__ __forceinline__ void gemm_compute(uint32_t st, int mrow, int ncol,
                                             int lane, float acc[4][4][4]) {
    int aRowL = lane & 15;
    int aCol8 = (lane >> 4) * 8;
    int bRowL = (lane & 7) + ((lane >> 4) & 1) * 8;
    int bCol8 = ((lane >> 3) & 1) * 8;
#pragma unroll
    for (int s = 0; s < 4; s++) {
        uint32_t A[4][4], B[2][4];
#pragma unroll
        for (int m = 0; m < 4; m++) {
            uint32_t off = (uint32_t)((mrow + m*16 + aRowL)*STRD + s*16 + aCol8) * 2;
            ldm4(A[m], st + off);
        }
#pragma unroll
        for (int p = 0; p < 2; p++) {
            uint32_t off = (uint32_t)((ncol + p*16 + bRowL)*STRD + s*16 + bCol8) * 2;
            ldm4(B[p], st + TILEB + off);
        }
#pragma unroll
        for (int m = 0; m < 4; m++)
#pragma unroll
            for (int n = 0; n < 4; n++)
                mma16816(acc[m][n], A[m], &B[n >> 1][(n & 1) * 2]);
    }
}

// ---------------- GEMM1 + GLU -> v (fp16) ----------------
__global__ void __launch_bounds__(256) k_gemm1(const float* __restrict__ b1) {
    int e  = blockIdx.z;
    int c0 = blockIdx.x * 128;
    if (c0 >= g_load[e]) return;
    int n0 = blockIdx.y * 64;            // 64 a-cols (+ paired 64 g-cols)
    extern __shared__ char sm[];
    uint32_t sb = smem_u32(sm);
    int t = threadIdx.x, lane = t & 31, w = t >> 5;
    int mrow = (w & 1) * 64, ncol = (w >> 1) * 32;

    size_t slotbase = (size_t)e*CAP + c0;
    const unsigned short* A  = g_xn + slotbase*DIM;
    const unsigned short* BG = g_w1 + (size_t)e*2*HH*DIM;

    float acc[4][4][4];
#pragma unroll
    for (int m = 0; m < 4; m++)
#pragma unroll
        for (int n = 0; n < 4; n++)
#pragma unroll
            for (int q = 0; q < 4; q++) acc[m][n][q] = 0.f;

    const int NT = DIM / BK;             // 16
    auto load_stage = [&](int kt, int buf) {
        int kb = kt * BK;
        uint32_t st = sb + buf*STAGEB;
        for (int i = t; i < 1024; i += 256) {
            int r = i >> 3, j = i & 7;
            uint32_t d = st + (uint32_t)(r*STRD*2 + j*16);
            cpa16(d, A + (size_t)r*DIM + kb + j*8);
            int col = (r < 64) ? (n0 + r) : (HH + n0 + r - 64);
            cpa16(d + TILEB, BG + (size_t)col*DIM + kb + j*8);
        }
    };

    load_stage(0, 0); CP_COMMIT();
    load_stage(1, 1); CP_COMMIT();
    for (int kt = 0; kt < NT; kt++) {
        if (kt + 1 < NT) { CP_WAIT(1); } else { CP_WAIT(0); }
        __syncthreads();
        if (kt + 2 < NT) { load_stage(kt + 2, (kt + 2) % 3); CP_COMMIT(); }
        gemm_compute(sb + (kt % 3)*STAGEB, mrow, ncol, lane, acc);
    }
    __syncthreads();

    // stage acc to smem [128][136] f32, then fused GLU
    float* sf = (float*)sm;
#pragma unroll
    for (int m = 0; m < 4; m++)
#pragma unroll
        for (int n = 0; n < 4; n++) {
            int row = mrow + m*16 + (lane >> 2);
            int col = ncol + n*8 + (lane & 3)*2;
            sf[row*136 + col]     = acc[m][n][0];
            sf[row*136 + col + 1] = acc[m][n][1];
            sf[(row+8)*136 + col]     = acc[m][n][2];
            sf[(row+8)*136 + col + 1] = acc[m][n][3];
        }
    __syncthreads();
    const float* b1a = b1 + (size_t)e*2*HH + n0;
    const float* b1g = b1a + HH;
    for (int i = t; i < 128*64; i += 256) {
        int m = i >> 6, j = i & 63;
        float a = sf[m*136 + j] + b1a[j];
        float g = sf[m*136 + 64 + j] + b1g[j];
        float v = a / (1.f + __expf(-g));
        g_v[(slotbase + m)*HH + n0 + j] = f2h(v);
    }
}

// ---------------- GEMM2 -> eo (fp32) ----------------
__global__ void __launch_bounds__(256) k_gemm2(const float* __restrict__ b2) {
    int e  = blockIdx.z;
    int c0 = blockIdx.x * 128;
    if (c0 >= g_load[e]) return;
    int n0 = blockIdx.y * 128;
    extern __shared__ char sm[];
    uint32_t sb = smem_u32(sm);
    int t = threadIdx.x, lane = t & 31, w = t >> 5;
    int mrow = (w & 1) * 64, ncol = (w >> 1) * 32;

    size_t slotbase = (size_t)e*CAP + c0;
    const unsigned short* A  = g_v + slotbase*HH;
    const unsigned short* BG = g_w2 + (size_t)e*DIM*HH;

    float acc[4][4][4];
#pragma unroll
    for (int m = 0; m < 4; m++)
#pragma unroll
        for (int n = 0; n < 4; n++)
#pragma unroll
            for (int q = 0; q < 4; q++) acc[m][n][q] = 0.f;

    const int NT = HH / BK;              // 64
    auto load_stage = [&](int kt, int buf) {
        int kb = kt * BK;
        uint32_t st = sb + buf*STAGEB;
        for (int i = t; i < 1024; i += 256) {
            int r = i >> 3, j = i & 7;
            uint32_t d = st + (uint32_t)(r*STRD*2 + j*16);
            cpa16(d, A + (size_t)r*HH + kb + j*8);
            int col = n0 + r;
            cpa16(d + TILEB, BG + (size_t)col*HH + kb + j*8);
        }
    };

    load_stage(0, 0); CP_COMMIT();
    load_stage(1, 1); CP_COMMIT();
    for (int kt = 0; kt < NT; kt++) {
        if (kt + 1 < NT) { CP_WAIT(1); } else { CP_WAIT(0); }
        __syncthreads();
        if (kt + 2 < NT) { load_stage(kt + 2, (kt + 2) % 3); CP_COMMIT(); }
        gemm_compute(sb + (kt % 3)*STAGEB, mrow, ncol, lane, acc);
    }

    const float* b2e = b2 + (size_t)e*DIM;
#pragma unroll
    for (int m = 0; m < 4; m++)
#pragma unroll
        for (int n = 0; n < 4; n++) {
            int row = mrow + m*16 + (lane >> 2);
            int col = n0 + ncol + n*8 + (lane & 3)*2;
            float2 v0 = make_float2(acc[m][n][0] + b2e[col], acc[m][n][1] + b2e[col+1]);
            float2 v1 = make_float2(acc[m][n][2] + b2e[col], acc[m][n][3] + b2e[col+1]);
            *(float2*)(g_eo + (slotbase + row)*DIM + col)     = v0;
            *(float2*)(g_eo + (slotbase + row + 8)*DIM + col) = v1;
        }
}

// ---------------- gather + combine -> y ----------------
__global__ void k_gather(float* __restrict__ out) {
    int n = blockIdx.x, t = threadIdx.x;
    int d = t * 4;
    float w0 = g_item_w[n], w1 = g_item_w[NTOK + n];
    float4 acc = make_float4(0.f, 0.f, 0.f, 0.f);
    if (w0 != 0.f) {
        int e = g_item_e[n], p = g_item_pos[n];
        float4 r = *(const float4*)(g_eo + ((size_t)e*CAP + p)*DIM + d);
        acc.x += w0*r.x; acc.y += w0*r.y; acc.z += w0*r.z; acc.w += w0*r.w;
    }
    if (w1 != 0.f) {
        int e = g_item_e[NTOK + n], p = g_item_pos[NTOK + n];
        float4 r = *(const float4*)(g_eo + ((size_t)e*CAP + p)*DIM + d);
        acc.x += w1*r.x; acc.y += w1*r.y; acc.z += w1*r.z; acc.w += w1*r.w;
    }
    *(float4*)(out + (size_t)n*DIM + d) = acc;
}

// ---------------- losses ----------------
__global__ void k_loss(float* __restrict__ out, int out_size) {
    if (threadIdx.x != 0) return;
    float imp[8]; float zs = 0.f;
#pragma unroll
    for (int e = 0; e < 8; e++) imp[e] = 0.f;
    for (int b = 0; b < 512; b++) {
        zs += g_pz[b];
#pragma unroll
        for (int e = 0; e < 8; e++) imp[e] += g_pimp[b*8 + e];
    }
    float z = zs / (float)(NTOK * NE) * 1e-4f;
    float m = 0.f;
#pragma unroll
    for (int e = 0; e < 8; e++) m += imp[e];
    m /= 8.f;
    float v = 0.f;
#pragma unroll
    for (int e = 0; e < 8; e++) { float d = imp[e] - m; v += d*d; }
    v /= 8.f;
    float mm = fmaxf(m, 1e-9f);
    float cvi = v / (mm*mm + 1e-9f);
    float ml = 0.f;
    float ld[8];
#pragma unroll
    for (int e = 0; e < 8; e++) { ld[e] = (float)g_load[e]; ml += ld[e]; }
    ml /= 8.f;
    float vl = 0.f;
#pragma unroll
    for (int e = 0; e < 8; e++) { float d = ld[e] - ml; vl += d*d; }
    vl /= 8.f;
    float mml = fmaxf(ml, 1e-9f);
    float cvl = vl / (mml*mml + 1e-9f);
    out[out_size - 2] = 0.5f * (cvi + cvl);
    out[out_size - 1] = z;
}

// ---------------- launch ----------------
extern "C" void kernel_launch(void* const* d_in, const int* in_sizes, int n_in,
                              void* d_out, int out_size) {
    const float* h   = (const float*)d_in[0];
    const float* Wr  = (const float*)d_in[1];
    const float* br  = (const float*)d_in[2];
    const float* lns = (const float*)d_in[3];
    const float* lnb = (const float*)d_in[4];
    const float* W1  = (const float*)d_in[5];
    const float* b1  = (const float*)d_in[6];
    const float* W2  = (const float*)d_in[7];
    const float* b2  = (const float*)d_in[8];
    float* out = (float*)d_out;

    cudaFuncSetAttribute(k_gemm1, cudaFuncAttributeMaxDynamicSharedMemorySize, SMEM_DYN);
    cudaFuncSetAttribute(k_gemm2, cudaFuncAttributeMaxDynamicSharedMemorySize, SMEM_DYN);

    // order: 4th launch (ncu target) = k_tw1
    k_router<<<NTOK/8, 256>>>(h, Wr, br);
    k_assign<<<1, 256>>>();
    k_ln<<<NE*CAP, 256>>>(h, lns, lnb);
    k_tw1<<<dim3(2*HH/64, DIM/64, NE), dim3(32, 8)>>>(W1);
    k_tw2<<<dim3(DIM/64, HH/64, NE), dim3(32, 8)>>>(W2);
    k_gemm1<<<dim3(CAP/128, HH/64, NE), 256, SMEM_DYN>>>(b1);
    k_gemm2<<<dim3(CAP/128, DIM/128, NE), 256, SMEM_DYN>>>(b2);
    k_gather<<<NTOK, 256>>>(out);
    k_loss<<<1, 32>>>(out, out_size);
}

// round 14
// speedup vs baseline: 1.1191x; 1.1191x over previous
#include <cuda_runtime.h>
#include <cuda_fp16.h>
#include <math.h>
#include <stdint.h>

#define NTOK 4096
#define DIM  1024
#define NE   8
#define HH   4096
#define CAP  1280
#define NK   (NTOK*2)

// GEMM tiling (R12-proven): warp 64x32, BK=64, 2-stage; all-fp16 operands
#define BK      64
#define STRD    72                    // smem row stride in fp16 elems (144 B)
#define TILEB   (128*STRD*2)          // 18432 B per tile (128 rows)
#define STAGEB  (2*TILEB)             // A, B = 36864 B
#define SMEM_DYN (2*STAGEB)           // 73728 B, 2 stages; 2+ CTA/SM

// ---------------- scratch (device globals; no allocations) ----------------
__device__ int   g_e0[NTOK], g_e1[NTOK];
__device__ float g_g0[NTOK], g_g1[NTOK];
__device__ int   g_item_e[NK];
__device__ int   g_item_pos[NK];
__device__ unsigned char g_item_keep[NK];
__device__ float g_item_w[NK];
__device__ int   g_slot_token[NE*CAP];
__device__ int   g_load[NE];
__device__ float g_pimp[512*NE];
__device__ float g_pz[512];

__device__ unsigned short g_xn[(size_t)NE*CAP*DIM];     // fp16
__device__ unsigned short g_w1[(size_t)NE*2*HH*DIM];    // fp16, transposed [e][n][k]
__device__ unsigned short g_w2[(size_t)NE*DIM*HH];      // fp16, transposed [e][n][k]
__device__ unsigned short g_v[(size_t)NE*CAP*HH];       // fp16
__device__ float g_eo[(size_t)NE*CAP*DIM];

// ---------------- helpers ----------------
__device__ __forceinline__ uint32_t smem_u32(const void* p) {
    uint32_t a;
    asm("{ .reg .u64 t; cvta.to.shared.u64 t, %1; cvt.u32.u64 %0, t; }" : "=r"(a) : "l"(p));
    return a;
}
__device__ __forceinline__ void cpa16(uint32_t dst, const void* src) {
    asm volatile("cp.async.ca.shared.global [%0], [%1], 16;" :: "r"(dst), "l"(src));
}
#define CP_COMMIT() asm volatile("cp.async.commit_group;" ::: "memory")
#define CP_WAIT(n)  asm volatile("cp.async.wait_group %0;" :: "n"(n) : "memory")

__device__ __forceinline__ void ldm4(uint32_t* r, uint32_t a) {
    asm volatile("ldmatrix.sync.aligned.m8n8.x4.shared.b16 {%0,%1,%2,%3}, [%4];"
        : "=r"(r[0]), "=r"(r[1]), "=r"(r[2]), "=r"(r[3]) : "r"(a));
}
__device__ __forceinline__ void mma16816(float* d, const uint32_t* a, const uint32_t* b0) {
    asm volatile("mma.sync.aligned.m16n8k16.row.col.f32.f16.f16.f32 "
        "{%0,%1,%2,%3}, {%4,%5,%6,%7}, {%8,%9}, {%0,%1,%2,%3};"
        : "+f"(d[0]), "+f"(d[1]), "+f"(d[2]), "+f"(d[3])
        : "r"(a[0]), "r"(a[1]), "r"(a[2]), "r"(a[3]), "r"(b0[0]), "r"(b0[1]));
}
__device__ __forceinline__ unsigned short f2h(float x) {
    __half hh = __float2half_rn(x);
    return *reinterpret_cast<unsigned short*>(&hh);
}

// ---------------- weight transpose + fp16: 64x64 tiles, packed writes -------
__global__ void k_tw1(const float* __restrict__ W) {
    __shared__ float tile[64][65];
    int e = blockIdx.z;
    int n0 = blockIdx.x * 64, k0 = blockIdx.y * 64;
    const float* S = W + (size_t)e * DIM * (2*HH);
    int tx = threadIdx.x, ty = threadIdx.y;
#pragma unroll
    for (int i = 0; i < 8; i++) {
        int kl = ty + i*8;
        const float* row = S + (size_t)(k0 + kl) * (2*HH) + n0;
        tile[kl][tx]      = row[tx];
        tile[kl][tx + 32] = row[tx + 32];
    }
    __syncthreads();
    size_t ob = (size_t)e * (2*HH) * DIM;
#pragma unroll
    for (int i = 0; i < 8; i++) {
        int nl = ty + i*8;
        unsigned short h0 = f2h(tile[tx*2][nl]);
        unsigned short h1 = f2h(tile[tx*2 + 1][nl]);
        size_t o = ob + (size_t)(n0 + nl) * DIM + k0;
        ((uint32_t*)(g_w1 + o))[tx] = (uint32_t)h0 | ((uint32_t)h1 << 16);
    }
}
__global__ void k_tw2(const float* __restrict__ W) {
    __shared__ float tile[64][65];
    int e = blockIdx.z;
    int n0 = blockIdx.x * 64, k0 = blockIdx.y * 64;
    const float* S = W + (size_t)e * HH * DIM;
    int tx = threadIdx.x, ty = threadIdx.y;
#pragma unroll
    for (int i = 0; i < 8; i++) {
        int kl = ty + i*8;
        const float* row = S + (size_t)(k0 + kl) * DIM + n0;
        tile[kl][tx]      = row[tx];
        tile[kl][tx + 32] = row[tx + 32];
    }
    __syncthreads();
    size_t ob = (size_t)e * DIM * HH;
#pragma unroll
    for (int i = 0; i < 8; i++) {
        int nl = ty + i*8;
        unsigned short h0 = f2h(tile[tx*2][nl]);
        unsigned short h1 = f2h(tile[tx*2 + 1][nl]);
        size_t o = ob + (size_t)(n0 + nl) * HH + k0;
        ((uint32_t*)(g_w2 + o))[tx] = (uint32_t)h0 | ((uint32_t)h1 << 16);
    }
}

// ---------------- router + fused stats ----------------
__global__ void k_router(const float* __restrict__ x, const float* __restrict__ Wr,
                         const float* __restrict__ br) {
    int warp = threadIdx.x >> 5, lane = threadIdx.x & 31;
    int n = blockIdx.x * 8 + warp;
    float acc[8];
#pragma unroll
    for (int j = 0; j < 8; j++) acc[j] = 0.f;
    const float* xr = x + (size_t)n * DIM;
    for (int d = lane; d < DIM; d += 32) {
        float xv = xr[d];
        float4 w0 = *(const float4*)(Wr + (size_t)d * 8);
        float4 w1 = *(const float4*)(Wr + (size_t)d * 8 + 4);
        acc[0] += xv * w0.x; acc[1] += xv * w0.y; acc[2] += xv * w0.z; acc[3] += xv * w0.w;
        acc[4] += xv * w1.x; acc[5] += xv * w1.y; acc[6] += xv * w1.z; acc[7] += xv * w1.w;
    }
#pragma unroll
    for (int off = 16; off; off >>= 1)
#pragma unroll
        for (int j = 0; j < 8; j++) acc[j] += __shfl_down_sync(0xffffffffu, acc[j], off);
    __shared__ float simp[8][8];
    __shared__ float simz[8];
    if (lane == 0) {
        float lg[8];
#pragma unroll
        for (int j = 0; j < 8; j++) lg[j] = acc[j] + br[j];
        int b0 = 0;
#pragma unroll
        for (int j = 1; j < 8; j++) if (lg[j] > lg[b0]) b0 = j;
        int b1 = (b0 == 0) ? 1 : 0;
#pragma unroll
        for (int j = 0; j < 8; j++) if (j != b0 && lg[j] > lg[b1]) b1 = j;
        g_e0[n] = b0; g_e1[n] = b1;
        float gg = 1.f / (1.f + expf(lg[b1] - lg[b0]));
        g_g0[n] = gg; g_g1[n] = 1.f - gg;
        float m = lg[0];
#pragma unroll
        for (int j = 1; j < 8; j++) m = fmaxf(m, lg[j]);
        float p[8], s = 0.f, zs = 0.f;
#pragma unroll
        for (int j = 0; j < 8; j++) { p[j] = expf(lg[j] - m); s += p[j]; zs += lg[j]*lg[j]; }
#pragma unroll
        for (int j = 0; j < 8; j++) simp[warp][j] = p[j] / s;
        simz[warp] = zs;
    }
    __syncthreads();
    if (threadIdx.x < 8) {
        float tsum = 0.f;
#pragma unroll
        for (int w2 = 0; w2 < 8; w2++) tsum += simp[w2][threadIdx.x];
        g_pimp[blockIdx.x*8 + threadIdx.x] = tsum;
    } else if (threadIdx.x == 8) {
        float tz = 0.f;
#pragma unroll
        for (int w2 = 0; w2 < 8; w2++) tz += simz[w2];
        g_pz[blockIdx.x] = tz;
    }
}

// ---------------- slot assignment ----------------
__global__ void k_assign() {
    __shared__ int scnt[256][NE];
    int t = threadIdx.x;
    int cnt[NE];
#pragma unroll
    for (int e = 0; e < NE; e++) cnt[e] = 0;
    int i0 = t * 32;
    for (int j = 0; j < 32; j++) {
        int i = i0 + j;
        int e = (i < NTOK) ? g_e0[i] : g_e1[i - NTOK];
        cnt[e]++;
    }
#pragma unroll
    for (int e = 0; e < NE; e++) scnt[t][e] = cnt[e];
    __syncthreads();
    if (t < NE) {
        int run = 0;
        for (int j = 0; j < 256; j++) { int tmp = scnt[j][t]; scnt[j][t] = run; run += tmp; }
        g_load[t] = (run < CAP) ? run : CAP;
    }
    __syncthreads();
    int off[NE];
#pragma unroll
    for (int e = 0; e < NE; e++) off[e] = scnt[t][e];
    for (int j = 0; j < 32; j++) {
        int i = i0 + j;
        int nn = (i < NTOK) ? i : (i - NTOK);
        int e  = (i < NTOK) ? g_e0[i] : g_e1[i - NTOK];
        int pos = off[e]++;
        int keep = (pos < CAP);
        g_item_e[i] = e;
        g_item_pos[i] = keep ? pos : (CAP - 1);
        g_item_keep[i] = (unsigned char)keep;
        if (keep) g_slot_token[e*CAP + pos] = nn;
    }
    __syncthreads();
    for (int n = t; n < NTOK; n += 256) {
        float kg0 = g_item_keep[n]        ? g_g0[n] : 0.f;
        float kg1 = g_item_keep[NTOK + n] ? g_g1[n] : 0.f;
        float denom = fmaxf(kg0 + kg1, 1e-8f);
        g_item_w[n] = kg0 / denom;
        g_item_w[NTOK + n] = kg1 / denom;
    }
}

// ---------------- gather + LayerNorm -> fp16 xn ----------------
__global__ void k_ln(const float* __restrict__ x, const float* __restrict__ lns,
                     const float* __restrict__ lnb) {
    int slot = blockIdx.x;
    int e = slot / CAP, c = slot % CAP;
    if (c >= g_load[e]) return;
    int token = g_slot_token[slot];
    int t = threadIdx.x;
    float4 xv = *(const float4*)(x + (size_t)token*DIM + t*4);
    float s = xv.x + xv.y + xv.z + xv.w;
    float q = xv.x*xv.x + xv.y*xv.y + xv.z*xv.z + xv.w*xv.w;
#pragma unroll
    for (int off = 16; off; off >>= 1) {
        s += __shfl_down_sync(0xffffffffu, s, off);
        q += __shfl_down_sync(0xffffffffu, q, off);
    }
    __shared__ float ws[8], wq[8];
    __shared__ float s_mu, s_rstd;
    int warp = t >> 5, lane = t & 31;
    if (lane == 0) { ws[warp] = s; wq[warp] = q; }
    __syncthreads();
    if (t == 0) {
        float S = 0.f, Q = 0.f;
#pragma unroll
        for (int w = 0; w < 8; w++) { S += ws[w]; Q += wq[w]; }
        float mu = S / DIM;
        float var = Q / DIM - mu*mu;
        s_mu = mu; s_rstd = rsqrtf(var + 1e-5f);
    }
    __syncthreads();
    float mu = s_mu, r = s_rstd;
    float4 sc = *(const float4*)(lns + (size_t)e*DIM + t*4);
    float4 bi = *(const float4*)(lnb + (size_t)e*DIM + t*4);
    unsigned short h[4];
    h[0] = f2h((xv.x - mu)*r*sc.x + bi.x);
    h[1] = f2h((xv.y - mu)*r*sc.y + bi.y);
    h[2] = f2h((xv.z - mu)*r*sc.z + bi.z);
    h[3] = f2h((xv.w - mu)*r*sc.w + bi.w);
    uint2 ph;
    ph.x = (uint32_t)h[0] | ((uint32_t)h[1] << 16);
    ph.y = (uint32_t)h[2] | ((uint32_t)h[3] << 16);
    *(uint2*)(g_xn + (size_t)slot*DIM + t*4) = ph;
}

// =======================================================================
// fp16 warp-MMA core (R12-proven): warp tile 64x32, BK=64, 2-stage.
// =======================================================================
__device__ __forceinline__ void gemm_compute(uint32_t st, int mrow, int ncol,
                                             int lane, float acc[4][4][4]) {
    int aRowL = lane & 15;
    int aCol8 = (lane >> 4) * 8;
    int bRowL = (lane & 7) + ((lane >> 4) & 1) * 8;
    int bCol8 = ((lane >> 3) & 1) * 8;
#pragma unroll
    for (int s = 0; s < 4; s++) {
        uint32_t A[4][4], B[2][4];
#pragma unroll
        for (int m = 0; m < 4; m++) {
            uint32_t off = (uint32_t)((mrow + m*16 + aRowL)*STRD + s*16 + aCol8) * 2;
            ldm4(A[m], st + off);
        }
#pragma unroll
        for (int p = 0; p < 2; p++) {
            uint32_t off = (uint32_t)((ncol + p*16 + bRowL)*STRD + s*16 + bCol8) * 2;
            ldm4(B[p], st + TILEB + off);
        }
#pragma unroll
        for (int m = 0; m < 4; m++)
#pragma unroll
            for (int n = 0; n < 4; n++)
                mma16816(acc[m][n], A[m], &B[n >> 1][(n & 1) * 2]);
    }
}

// ---------------- GEMM1 + register GLU -> v (fp16) ----------------
// B tile rows interleave a/g: group g32 = r>>5 (4 groups), idx = r&31;
// idx<16 -> a-col n0+g32*16+idx ; idx>=16 -> g-col HH+n0+g32*16+(idx-16).
// Warp (ncol = (w>>1)*32) owns one group; acc[m][n] (n<2, a) pairs with
// acc[m][n+2] (g) at the SAME output (row, col).
__global__ void __launch_bounds__(256) k_gemm1(const float* __restrict__ b1) {
    int e  = blockIdx.z;
    int c0 = blockIdx.x * 128;
    if (c0 >= g_load[e]) return;
    int n0 = blockIdx.y * 64;            // 64 a-cols (+ paired 64 g-cols)
    extern __shared__ char sm[];
    uint32_t sb = smem_u32(sm);
    int t = threadIdx.x, lane = t & 31, w = t >> 5;
    int mrow = (w & 1) * 64, ncol = (w >> 1) * 32;
    int grp = (w >> 1);

    size_t slotbase = (size_t)e*CAP + c0;
    const unsigned short* A  = g_xn + slotbase*DIM;
    const unsigned short* BG = g_w1 + (size_t)e*2*HH*DIM;

    float acc[4][4][4];
#pragma unroll
    for (int m = 0; m < 4; m++)
#pragma unroll
        for (int n = 0; n < 4; n++)
#pragma unroll
            for (int q = 0; q < 4; q++) acc[m][n][q] = 0.f;

    const int NT = DIM / BK;             // 16
    auto load_stage = [&](int kt, int buf) {
        int kb = kt * BK;
        uint32_t st = sb + buf*STAGEB;
        for (int i = t; i < 1024; i += 256) {
            int r = i >> 3, j = i & 7;
            uint32_t d = st + (uint32_t)(r*STRD*2 + j*16);
            cpa16(d, A + (size_t)r*DIM + kb + j*8);
            int g32 = r >> 5, idx = r & 31;
            int col = (idx < 16) ? (n0 + g32*16 + idx)
                                 : (HH + n0 + g32*16 + (idx - 16));
            cpa16(d + TILEB, BG + (size_t)col*DIM + kb + j*8);
        }
    };

    load_stage(0, 0); CP_COMMIT();
    for (int kt = 0; kt < NT; kt++) {
        int buf = kt & 1;
        if (kt + 1 < NT) { load_stage(kt + 1, buf ^ 1); CP_COMMIT(); CP_WAIT(1); }
        else CP_WAIT(0);
        __syncthreads();
        gemm_compute(sb + buf*STAGEB, mrow, ncol, lane, acc);
        __syncthreads();
    }

    // register GLU epilogue: no smem, no syncs
    int colbase = n0 + grp*16;
    const float* b1a = b1 + (size_t)e*2*HH;
    const float* b1g = b1a + HH;
#pragma unroll
    for (int n = 0; n < 2; n++) {
        int col = colbase + n*8 + (lane & 3)*2;
        float ba0 = b1a[col], ba1 = b1a[col+1];
        float bg0 = b1g[col], bg1 = b1g[col+1];
#pragma unroll
        for (int m = 0; m < 4; m++) {
            int row = mrow + m*16 + (lane >> 2);
            float a0 = acc[m][n][0] + ba0, a1 = acc[m][n][1] + ba1;
            float q0 = acc[m][n+2][0] + bg0, q1 = acc[m][n+2][1] + bg1;
            float v0 = a0 / (1.f + __expf(-q0));
            float v1 = a1 / (1.f + __expf(-q1));
            *(uint32_t*)(g_v + (slotbase + row)*HH + col) =
                (uint32_t)f2h(v0) | ((uint32_t)f2h(v1) << 16);
            a0 = acc[m][n][2] + ba0; a1 = acc[m][n][3] + ba1;
            q0 = acc[m][n+2][2] + bg0; q1 = acc[m][n+2][3] + bg1;
            v0 = a0 / (1.f + __expf(-q0));
            v1 = a1 / (1.f + __expf(-q1));
            *(uint32_t*)(g_v + (slotbase + row + 8)*HH + col) =
                (uint32_t)f2h(v0) | ((uint32_t)f2h(v1) << 16);
        }
    }
}

// ---------------- GEMM2 -> eo (fp32) ----------------
__global__ void __launch_bounds__(256) k_gemm2(const float* __restrict__ b2) {
    int e  = blockIdx.z;
    int c0 = blockIdx.x * 128;
    if (c0 >= g_load[e]) return;
    int n0 = blockIdx.y * 128;
    extern __shared__ char sm[];
    uint32_t sb = smem_u32(sm);
    int t = threadIdx.x, lane = t & 31, w = t >> 5;
    int mrow = (w & 1) * 64, ncol = (w >> 1) * 32;

    size_t slotbase = (size_t)e*CAP + c0;
    const unsigned short* A  = g_v + slotbase*HH;
    const unsigned short* BG = g_w2 + (size_t)e*DIM*HH;

    float acc[4][4][4];
#pragma unroll
    for (int m = 0; m < 4; m++)
#pragma unroll
        for (int n = 0; n < 4; n++)
#pragma unroll
            for (int q = 0; q < 4; q++) acc[m][n][q] = 0.f;

    const int NT = HH / BK;              // 64
    auto load_stage = [&](int kt, int buf) {
        int kb = kt * BK;
        uint32_t st = sb + buf*STAGEB;
        for (int i = t; i < 1024; i += 256) {
            int r = i >> 3, j = i & 7;
            uint32_t d = st + (uint32_t)(r*STRD*2 + j*16);
            cpa16(d, A + (size_t)r*HH + kb + j*8);
            int col = n0 + r;
            cpa16(d + TILEB, BG + (size_t)col*HH + kb + j*8);
        }
    };

    load_stage(0, 0); CP_COMMIT();
    for (int kt = 0; kt < NT; kt++) {
        int buf = kt & 1;
        if (kt + 1 < NT) { load_stage(kt + 1, buf ^ 1); CP_COMMIT(); CP_WAIT(1); }
        else CP_WAIT(0);
        __syncthreads();
        gemm_compute(sb + buf*STAGEB, mrow, ncol, lane, acc);
        __syncthreads();
    }

    const float* b2e = b2 + (size_t)e*DIM;
#pragma unroll
    for (int m = 0; m < 4; m++)
#pragma unroll
        for (int n = 0; n < 4; n++) {
            int row = mrow + m*16 + (lane >> 2);
            int col = n0 + ncol + n*8 + (lane & 3)*2;
            float2 v0 = make_float2(acc[m][n][0] + b2e[col], acc[m][n][1] + b2e[col+1]);
            float2 v1 = make_float2(acc[m][n][2] + b2e[col], acc[m][n][3] + b2e[col+1]);
            *(float2*)(g_eo + (slotbase + row)*DIM + col)     = v0;
            *(float2*)(g_eo + (slotbase + row + 8)*DIM + col) = v1;
        }
}

// ---------------- gather + combine -> y ----------------
__global__ void k_gather(float* __restrict__ out) {
    int n = blockIdx.x, t = threadIdx.x;
    int d = t * 4;
    float w0 = g_item_w[n], w1 = g_item_w[NTOK + n];
    float4 acc = make_float4(0.f, 0.f, 0.f, 0.f);
    if (w0 != 0.f) {
        int e = g_item_e[n], p = g_item_pos[n];
        float4 r = *(const float4*)(g_eo + ((size_t)e*CAP + p)*DIM + d);
        acc.x += w0*r.x; acc.y += w0*r.y; acc.z += w0*r.z; acc.w += w0*r.w;
    }
    if (w1 != 0.f) {
        int e = g_item_e[NTOK + n], p = g_item_pos[NTOK + n];
        float4 r = *(const float4*)(g_eo + ((size_t)e*CAP + p)*DIM + d);
        acc.x += w1*r.x; acc.y += w1*r.y; acc.z += w1*r.z; acc.w += w1*r.w;
    }
    *(float4*)(out + (size_t)n*DIM + d) = acc;
}

// ---------------- losses ----------------
__global__ void k_loss(float* __restrict__ out, int out_size) {
    if (threadIdx.x != 0) return;
    float imp[8]; float zs = 0.f;
#pragma unroll
    for (int e = 0; e < 8; e++) imp[e] = 0.f;
    for (int b = 0; b < 512; b++) {
        zs += g_pz[b];
#pragma unroll
        for (int e = 0; e < 8; e++) imp[e] += g_pimp[b*8 + e];
    }
    float z = zs / (float)(NTOK * NE) * 1e-4f;
    float m = 0.f;
#pragma unroll
    for (int e = 0; e < 8; e++) m += imp[e];
    m /= 8.f;
    float v = 0.f;
#pragma unroll
    for (int e = 0; e < 8; e++) { float d = imp[e] - m; v += d*d; }
    v /= 8.f;
    float mm = fmaxf(m, 1e-9f);
    float cvi = v / (mm*mm + 1e-9f);
    float ml = 0.f;
    float ld[8];
#pragma unroll
    for (int e = 0; e < 8; e++) { ld[e] = (float)g_load[e]; ml += ld[e]; }
    ml /= 8.f;
    float vl = 0.f;
#pragma unroll
    for (int e = 0; e < 8; e++) { float d = ld[e] - ml; vl += d*d; }
    vl /= 8.f;
    float mml = fmaxf(ml, 1e-9f);
    float cvl = vl / (mml*mml + 1e-9f);
    out[out_size - 2] = 0.5f * (cvi + cvl);
    out[out_size - 1] = z;
}

// ---------------- launch ----------------
extern "C" void kernel_launch(void* const* d_in, const int* in_sizes, int n_in,
                              void* d_out, int out_size) {
    const float* h   = (const float*)d_in[0];
    const float* Wr  = (const float*)d_in[1];
    const float* br  = (const float*)d_in[2];
    const float* lns = (const float*)d_in[3];
    const float* lnb = (const float*)d_in[4];
    const float* W1  = (const float*)d_in[5];
    const float* b1  = (const float*)d_in[6];
    const float* W2  = (const float*)d_in[7];
    const float* b2  = (const float*)d_in[8];
    float* out = (float*)d_out;

    cudaFuncSetAttribute(k_gemm1, cudaFuncAttributeMaxDynamicSharedMemorySize, SMEM_DYN);
    cudaFuncSetAttribute(k_gemm2, cudaFuncAttributeMaxDynamicSharedMemorySize, SMEM_DYN);

    // order: 4th launch (ncu target) = k_tw1
    k_router<<<NTOK/8, 256>>>(h, Wr, br);
    k_assign<<<1, 256>>>();
    k_ln<<<NE*CAP, 256>>>(h, lns, lnb);
    k_tw1<<<dim3(2*HH/64, DIM/64, NE), dim3(32, 8)>>>(W1);
    k_tw2<<<dim3(DIM/64, HH/64, NE), dim3(32, 8)>>>(W2);
    k_gemm1<<<dim3(CAP/128, HH/64, NE), 256, SMEM_DYN>>>(b1);
    k_gemm2<<<dim3(CAP/128, DIM/128, NE), 256, SMEM_DYN>>>(b2);
    k_gather<<<NTOK, 256>>>(out);
    k_loss<<<1, 32>>>(out, out_size);
}

// round 15
// speedup vs baseline: 1.1263x; 1.0064x over previous
#include <cuda_runtime.h>
#include <cuda_fp16.h>
#include <math.h>
#include <stdint.h>

#define NTOK 4096
#define DIM  1024
#define NE   8
#define HH   4096
#define CAP  1280
#define NK   (NTOK*2)

// GEMM tiling (R12/R14-proven): warp 64x32, BK=64, 2-stage; all-fp16 operands
#define BK      64
#define STRD    72                    // smem row stride in fp16 elems (144 B)
#define TILEB   (128*STRD*2)          // 18432 B per tile (128 rows)
#define STAGEB  (2*TILEB)             // A, B = 36864 B
#define SMEM_DYN (2*STAGEB)           // 73728 B, 2 stages; 2+ CTA/SM

// ---------------- scratch (device globals; no allocations) ----------------
__device__ int   g_e0[NTOK], g_e1[NTOK];
__device__ float g_g0[NTOK], g_g1[NTOK];
__device__ int   g_item_e[NK];
__device__ int   g_item_pos[NK];
__device__ unsigned char g_item_keep[NK];
__device__ float g_item_w[NK];
__device__ int   g_slot_token[NE*CAP];
__device__ int   g_load[NE];
__device__ float g_pimp[512*NE];
__device__ float g_pz[512];

__device__ unsigned short g_xn[(size_t)NE*CAP*DIM];     // fp16
__device__ unsigned short g_w1[(size_t)NE*2*HH*DIM];    // fp16, transposed [e][n][k]
__device__ unsigned short g_w2[(size_t)NE*DIM*HH];      // fp16, transposed [e][n][k]
__device__ unsigned short g_v[(size_t)NE*CAP*HH];       // fp16
__device__ float g_eo[(size_t)NE*CAP*DIM];

// ---------------- helpers ----------------
__device__ __forceinline__ uint32_t smem_u32(const void* p) {
    uint32_t a;
    asm("{ .reg .u64 t; cvta.to.shared.u64 t, %1; cvt.u32.u64 %0, t; }" : "=r"(a) : "l"(p));
    return a;
}
__device__ __forceinline__ void cpa16(uint32_t dst, const void* src) {
    asm volatile("cp.async.ca.shared.global [%0], [%1], 16;" :: "r"(dst), "l"(src));
}
#define CP_COMMIT() asm volatile("cp.async.commit_group;" ::: "memory")
#define CP_WAIT(n)  asm volatile("cp.async.wait_group %0;" :: "n"(n) : "memory")

__device__ __forceinline__ void ldm4(uint32_t* r, uint32_t a) {
    asm volatile("ldmatrix.sync.aligned.m8n8.x4.shared.b16 {%0,%1,%2,%3}, [%4];"
        : "=r"(r[0]), "=r"(r[1]), "=r"(r[2]), "=r"(r[3]) : "r"(a));
}
__device__ __forceinline__ void mma16816(float* d, const uint32_t* a, const uint32_t* b0) {
    asm volatile("mma.sync.aligned.m16n8k16.row.col.f32.f16.f16.f32 "
        "{%0,%1,%2,%3}, {%4,%5,%6,%7}, {%8,%9}, {%0,%1,%2,%3};"
        : "+f"(d[0]), "+f"(d[1]), "+f"(d[2]), "+f"(d[3])
        : "r"(a[0]), "r"(a[1]), "r"(a[2]), "r"(a[3]), "r"(b0[0]), "r"(b0[1]));
}
__device__ __forceinline__ unsigned short f2h(float x) {
    __half hh = __float2half_rn(x);
    return *reinterpret_cast<unsigned short*>(&hh);
}

// ---------------- weight transpose + fp16: 64x64 tiles, packed writes -------
__global__ void k_tw1(const float* __restrict__ W) {
    __shared__ float tile[64][65];
    int e = blockIdx.z;
    int n0 = blockIdx.x * 64, k0 = blockIdx.y * 64;
    const float* S = W + (size_t)e * DIM * (2*HH);
    int tx = threadIdx.x, ty = threadIdx.y;
#pragma unroll
    for (int i = 0; i < 8; i++) {
        int kl = ty + i*8;
        const float* row = S + (size_t)(k0 + kl) * (2*HH) + n0;
        tile[kl][tx]      = row[tx];
        tile[kl][tx + 32] = row[tx + 32];
    }
    __syncthreads();
    size_t ob = (size_t)e * (2*HH) * DIM;
#pragma unroll
    for (int i = 0; i < 8; i++) {
        int nl = ty + i*8;
        unsigned short h0 = f2h(tile[tx*2][nl]);
        unsigned short h1 = f2h(tile[tx*2 + 1][nl]);
        size_t o = ob + (size_t)(n0 + nl) * DIM + k0;
        ((uint32_t*)(g_w1 + o))[tx] = (uint32_t)h0 | ((uint32_t)h1 << 16);
    }
}
__global__ void k_tw2(const float* __restrict__ W) {
    __shared__ float tile[64][65];
    int e = blockIdx.z;
    int n0 = blockIdx.x * 64, k0 = blockIdx.y * 64;
    const float* S = W + (size_t)e * HH * DIM;
    int tx = threadIdx.x, ty = threadIdx.y;
#pragma unroll
    for (int i = 0; i < 8; i++) {
        int kl = ty + i*8;
        const float* row = S + (size_t)(k0 + kl) * DIM + n0;
        tile[kl][tx]      = row[tx];
        tile[kl][tx + 32] = row[tx + 32];
    }
    __syncthreads();
    size_t ob = (size_t)e * DIM * HH;
#pragma unroll
    for (int i = 0; i < 8; i++) {
        int nl = ty + i*8;
        unsigned short h0 = f2h(tile[tx*2][nl]);
        unsigned short h1 = f2h(tile[tx*2 + 1][nl]);
        size_t o = ob + (size_t)(n0 + nl) * HH + k0;
        ((uint32_t*)(g_w2 + o))[tx] = (uint32_t)h0 | ((uint32_t)h1 << 16);
    }
}

// ---------------- router + fused stats ----------------
__global__ void k_router(const float* __restrict__ x, const float* __restrict__ Wr,
                         const float* __restrict__ br) {
    int warp = threadIdx.x >> 5, lane = threadIdx.x & 31;
    int n = blockIdx.x * 8 + warp;
    float acc[8];
#pragma unroll
    for (int j = 0; j < 8; j++) acc[j] = 0.f;
    const float* xr = x + (size_t)n * DIM;
    for (int d = lane; d < DIM; d += 32) {
        float xv = xr[d];
        float4 w0 = *(const float4*)(Wr + (size_t)d * 8);
        float4 w1 = *(const float4*)(Wr + (size_t)d * 8 + 4);
        acc[0] += xv * w0.x; acc[1] += xv * w0.y; acc[2] += xv * w0.z; acc[3] += xv * w0.w;
        acc[4] += xv * w1.x; acc[5] += xv * w1.y; acc[6] += xv * w1.z; acc[7] += xv * w1.w;
    }
#pragma unroll
    for (int off = 16; off; off >>= 1)
#pragma unroll
        for (int j = 0; j < 8; j++) acc[j] += __shfl_down_sync(0xffffffffu, acc[j], off);
    __shared__ float simp[8][8];
    __shared__ float simz[8];
    if (lane == 0) {
        float lg[8];
#pragma unroll
        for (int j = 0; j < 8; j++) lg[j] = acc[j] + br[j];
        int b0 = 0;
#pragma unroll
        for (int j = 1; j < 8; j++) if (lg[j] > lg[b0]) b0 = j;
        int b1 = (b0 == 0) ? 1 : 0;
#pragma unroll
        for (int j = 0; j < 8; j++) if (j != b0 && lg[j] > lg[b1]) b1 = j;
        g_e0[n] = b0; g_e1[n] = b1;
        float gg = 1.f / (1.f + expf(lg[b1] - lg[b0]));
        g_g0[n] = gg; g_g1[n] = 1.f - gg;
        float m = lg[0];
#pragma unroll
        for (int j = 1; j < 8; j++) m = fmaxf(m, lg[j]);
        float p[8], s = 0.f, zs = 0.f;
#pragma unroll
        for (int j = 0; j < 8; j++) { p[j] = expf(lg[j] - m); s += p[j]; zs += lg[j]*lg[j]; }
#pragma unroll
        for (int j = 0; j < 8; j++) simp[warp][j] = p[j] / s;
        simz[warp] = zs;
    }
    __syncthreads();
    if (threadIdx.x < 8) {
        float tsum = 0.f;
#pragma unroll
        for (int w2 = 0; w2 < 8; w2++) tsum += simp[w2][threadIdx.x];
        g_pimp[blockIdx.x*8 + threadIdx.x] = tsum;
    } else if (threadIdx.x == 8) {
        float tz = 0.f;
#pragma unroll
        for (int w2 = 0; w2 < 8; w2++) tz += simz[w2];
        g_pz[blockIdx.x] = tz;
    }
}

// ---------------- slot assignment ----------------
__global__ void k_assign() {
    __shared__ int scnt[256][NE];
    int t = threadIdx.x;
    int cnt[NE];
#pragma unroll
    for (int e = 0; e < NE; e++) cnt[e] = 0;
    int i0 = t * 32;
    for (int j = 0; j < 32; j++) {
        int i = i0 + j;
        int e = (i < NTOK) ? g_e0[i] : g_e1[i - NTOK];
        cnt[e]++;
    }
#pragma unroll
    for (int e = 0; e < NE; e++) scnt[t][e] = cnt[e];
    __syncthreads();
    if (t < NE) {
        int run = 0;
        for (int j = 0; j < 256; j++) { int tmp = scnt[j][t]; scnt[j][t] = run; run += tmp; }
        g_load[t] = (run < CAP) ? run : CAP;
    }
    __syncthreads();
    int off[NE];
#pragma unroll
    for (int e = 0; e < NE; e++) off[e] = scnt[t][e];
    for (int j = 0; j < 32; j++) {
        int i = i0 + j;
        int nn = (i < NTOK) ? i : (i - NTOK);
        int e  = (i < NTOK) ? g_e0[i] : g_e1[i - NTOK];
        int pos = off[e]++;
        int keep = (pos < CAP);
        g_item_e[i] = e;
        g_item_pos[i] = keep ? pos : (CAP - 1);
        g_item_keep[i] = (unsigned char)keep;
        if (keep) g_slot_token[e*CAP + pos] = nn;
    }
    __syncthreads();
    for (int n = t; n < NTOK; n += 256) {
        float kg0 = g_item_keep[n]        ? g_g0[n] : 0.f;
        float kg1 = g_item_keep[NTOK + n] ? g_g1[n] : 0.f;
        float denom = fmaxf(kg0 + kg1, 1e-8f);
        g_item_w[n] = kg0 / denom;
        g_item_w[NTOK + n] = kg1 / denom;
    }
}

// ---------------- gather + LayerNorm -> fp16 xn ----------------
__global__ void k_ln(const float* __restrict__ x, const float* __restrict__ lns,
                     const float* __restrict__ lnb) {
    int slot = blockIdx.x;
    int e = slot / CAP, c = slot % CAP;
    if (c >= g_load[e]) return;
    int token = g_slot_token[slot];
    int t = threadIdx.x;
    float4 xv = *(const float4*)(x + (size_t)token*DIM + t*4);
    float s = xv.x + xv.y + xv.z + xv.w;
    float q = xv.x*xv.x + xv.y*xv.y + xv.z*xv.z + xv.w*xv.w;
#pragma unroll
    for (int off = 16; off; off >>= 1) {
        s += __shfl_down_sync(0xffffffffu, s, off);
        q += __shfl_down_sync(0xffffffffu, q, off);
    }
    __shared__ float ws[8], wq[8];
    __shared__ float s_mu, s_rstd;
    int warp = t >> 5, lane = t & 31;
    if (lane == 0) { ws[warp] = s; wq[warp] = q; }
    __syncthreads();
    if (t == 0) {
        float S = 0.f, Q = 0.f;
#pragma unroll
        for (int w = 0; w < 8; w++) { S += ws[w]; Q += wq[w]; }
        float mu = S / DIM;
        float var = Q / DIM - mu*mu;
        s_mu = mu; s_rstd = rsqrtf(var + 1e-5f);
    }
    __syncthreads();
    float mu = s_mu, r = s_rstd;
    float4 sc = *(const float4*)(lns + (size_t)e*DIM + t*4);
    float4 bi = *(const float4*)(lnb + (size_t)e*DIM + t*4);
    unsigned short h[4];
    h[0] = f2h((xv.x - mu)*r*sc.x + bi.x);
    h[1] = f2h((xv.y - mu)*r*sc.y + bi.y);
    h[2] = f2h((xv.z - mu)*r*sc.z + bi.z);
    h[3] = f2h((xv.w - mu)*r*sc.w + bi.w);
    uint2 ph;
    ph.x = (uint32_t)h[0] | ((uint32_t)h[1] << 16);
    ph.y = (uint32_t)h[2] | ((uint32_t)h[3] << 16);
    *(uint2*)(g_xn + (size_t)slot*DIM + t*4) = ph;
}

// =======================================================================
// fp16 warp-MMA core (proven): warp tile 64x32, BK=64, 2-stage.
// =======================================================================
__device__ __forceinline__ void gemm_compute(uint32_t st, int mrow, int ncol,
                                             int lane, float acc[4][4][4]) {
    int aRowL = lane & 15;
    int aCol8 = (lane >> 4) * 8;
    int bRowL = (lane & 7) + ((lane >> 4) & 1) * 8;
    int bCol8 = ((lane >> 3) & 1) * 8;
#pragma unroll
    for (int s = 0; s < 4; s++) {
        uint32_t A[4][4], B[2][4];
#pragma unroll
        for (int m = 0; m < 4; m++) {
            uint32_t off = (uint32_t)((mrow + m*16 + aRowL)*STRD + s*16 + aCol8) * 2;
            ldm4(A[m], st + off);
        }
#pragma unroll
        for (int p = 0; p < 2; p++) {
            uint32_t off = (uint32_t)((ncol + p*16 + bRowL)*STRD + s*16 + bCol8) * 2;
            ldm4(B[p], st + TILEB + off);
        }
#pragma unroll
        for (int m = 0; m < 4; m++)
#pragma unroll
            for (int n = 0; n < 4; n++)
                mma16816(acc[m][n], A[m], &B[n >> 1][(n & 1) * 2]);
    }
}

// ---------------- GEMM1 + register GLU -> v (fp16) ----------------
__global__ void __launch_bounds__(256) k_gemm1(const float* __restrict__ b1) {
    int e  = blockIdx.z;
    int c0 = blockIdx.x * 128;
    if (c0 >= g_load[e]) return;
    int n0 = blockIdx.y * 64;            // 64 a-cols (+ paired 64 g-cols)
    extern __shared__ char sm[];
    uint32_t sb = smem_u32(sm);
    int t = threadIdx.x, lane = t & 31, w = t >> 5;
    int mrow = (w & 1) * 64, ncol = (w >> 1) * 32;
    int grp = (w >> 1);

    size_t slotbase = (size_t)e*CAP + c0;
    const unsigned short* A  = g_xn + slotbase*DIM;
    const unsigned short* BG = g_w1 + (size_t)e*2*HH*DIM;

    float acc[4][4][4];
#pragma unroll
    for (int m = 0; m < 4; m++)
#pragma unroll
        for (int n = 0; n < 4; n++)
#pragma unroll
            for (int q = 0; q < 4; q++) acc[m][n][q] = 0.f;

    const int NT = DIM / BK;             // 16
    auto load_stage = [&](int kt, int buf) {
        int kb = kt * BK;
        uint32_t st = sb + buf*STAGEB;
        for (int i = t; i < 1024; i += 256) {
            int r = i >> 3, j = i & 7;
            uint32_t d = st + (uint32_t)(r*STRD*2 + j*16);
            cpa16(d, A + (size_t)r*DIM + kb + j*8);
            int g32 = r >> 5, idx = r & 31;
            int col = (idx < 16) ? (n0 + g32*16 + idx)
                                 : (HH + n0 + g32*16 + (idx - 16));
            cpa16(d + TILEB, BG + (size_t)col*DIM + kb + j*8);
        }
    };

    load_stage(0, 0); CP_COMMIT();
    for (int kt = 0; kt < NT; kt++) {
        int buf = kt & 1;
        if (kt + 1 < NT) { load_stage(kt + 1, buf ^ 1); CP_COMMIT(); CP_WAIT(1); }
        else CP_WAIT(0);
        __syncthreads();
        gemm_compute(sb + buf*STAGEB, mrow, ncol, lane, acc);
        __syncthreads();
    }

    // register GLU epilogue: no smem, no syncs
    int colbase = n0 + grp*16;
    const float* b1a = b1 + (size_t)e*2*HH;
    const float* b1g = b1a + HH;
#pragma unroll
    for (int n = 0; n < 2; n++) {
        int col = colbase + n*8 + (lane & 3)*2;
        float ba0 = b1a[col], ba1 = b1a[col+1];
        float bg0 = b1g[col], bg1 = b1g[col+1];
#pragma unroll
        for (int m = 0; m < 4; m++) {
            int row = mrow + m*16 + (lane >> 2);
            float a0 = acc[m][n][0] + ba0, a1 = acc[m][n][1] + ba1;
            float q0 = acc[m][n+2][0] + bg0, q1 = acc[m][n+2][1] + bg1;
            float v0 = a0 / (1.f + __expf(-q0));
            float v1 = a1 / (1.f + __expf(-q1));
            *(uint32_t*)(g_v + (slotbase + row)*HH + col) =
                (uint32_t)f2h(v0) | ((uint32_t)f2h(v1) << 16);
            a0 = acc[m][n][2] + ba0; a1 = acc[m][n][3] + ba1;
            q0 = acc[m][n+2][2] + bg0; q1 = acc[m][n+2][3] + bg1;
            v0 = a0 / (1.f + __expf(-q0));
            v1 = a1 / (1.f + __expf(-q1));
            *(uint32_t*)(g_v + (slotbase + row + 8)*HH + col) =
                (uint32_t)f2h(v0) | ((uint32_t)f2h(v1) << 16);
        }
    }
}

// ---------------- GEMM2 -> eo (fp32) ----------------
__global__ void __launch_bounds__(256) k_gemm2(const float* __restrict__ b2) {
    int e  = blockIdx.z;
    int c0 = blockIdx.x * 128;
    if (c0 >= g_load[e]) return;
    int n0 = blockIdx.y * 128;
    extern __shared__ char sm[];
    uint32_t sb = smem_u32(sm);
    int t = threadIdx.x, lane = t & 31, w = t >> 5;
    int mrow = (w & 1) * 64, ncol = (w >> 1) * 32;

    size_t slotbase = (size_t)e*CAP + c0;
    const unsigned short* A  = g_v + slotbase*HH;
    const unsigned short* BG = g_w2 + (size_t)e*DIM*HH;

    float acc[4][4][4];
#pragma unroll
    for (int m = 0; m < 4; m++)
#pragma unroll
        for (int n = 0; n < 4; n++)
#pragma unroll
            for (int q = 0; q < 4; q++) acc[m][n][q] = 0.f;

    const int NT = HH / BK;              // 64
    auto load_stage = [&](int kt, int buf) {
        int kb = kt * BK;
        uint32_t st = sb + buf*STAGEB;
        for (int i = t; i < 1024; i += 256) {
            int r = i >> 3, j = i & 7;
            uint32_t d = st + (uint32_t)(r*STRD*2 + j*16);
            cpa16(d, A + (size_t)r*HH + kb + j*8);
            int col = n0 + r;
            cpa16(d + TILEB, BG + (size_t)col*HH + kb + j*8);
        }
    };

    load_stage(0, 0); CP_COMMIT();
    for (int kt = 0; kt < NT; kt++) {
        int buf = kt & 1;
        if (kt + 1 < NT) { load_stage(kt + 1, buf ^ 1); CP_COMMIT(); CP_WAIT(1); }
        else CP_WAIT(0);
        __syncthreads();
        gemm_compute(sb + buf*STAGEB, mrow, ncol, lane, acc);
        __syncthreads();
    }

    const float* b2e = b2 + (size_t)e*DIM;
#pragma unroll
    for (int m = 0; m < 4; m++)
#pragma unroll
        for (int n = 0; n < 4; n++) {
            int row = mrow + m*16 + (lane >> 2);
            int col = n0 + ncol + n*8 + (lane & 3)*2;
            float2 v0 = make_float2(acc[m][n][0] + b2e[col], acc[m][n][1] + b2e[col+1]);
            float2 v1 = make_float2(acc[m][n][2] + b2e[col], acc[m][n][3] + b2e[col+1]);
            *(float2*)(g_eo + (slotbase + row)*DIM + col)     = v0;
            *(float2*)(g_eo + (slotbase + row + 8)*DIM + col) = v1;
        }
}

// ---------------- gather + combine -> y ----------------
__global__ void k_gather(float* __restrict__ out) {
    int n = blockIdx.x, t = threadIdx.x;
    int d = t * 4;
    float w0 = g_item_w[n], w1 = g_item_w[NTOK + n];
    float4 acc = make_float4(0.f, 0.f, 0.f, 0.f);
    if (w0 != 0.f) {
        int e = g_item_e[n], p = g_item_pos[n];
        float4 r = *(const float4*)(g_eo + ((size_t)e*CAP + p)*DIM + d);
        acc.x += w0*r.x; acc.y += w0*r.y; acc.z += w0*r.z; acc.w += w0*r.w;
    }
    if (w1 != 0.f) {
        int e = g_item_e[NTOK + n], p = g_item_pos[NTOK + n];
        float4 r = *(const float4*)(g_eo + ((size_t)e*CAP + p)*DIM + d);
        acc.x += w1*r.x; acc.y += w1*r.y; acc.z += w1*r.z; acc.w += w1*r.w;
    }
    *(float4*)(out + (size_t)n*DIM + d) = acc;
}

// ---------------- losses ----------------
__global__ void k_loss(float* __restrict__ out, int out_size) {
    if (threadIdx.x != 0) return;
    float imp[8]; float zs = 0.f;
#pragma unroll
    for (int e = 0; e < 8; e++) imp[e] = 0.f;
    for (int b = 0; b < 512; b++) {
        zs += g_pz[b];
#pragma unroll
        for (int e = 0; e < 8; e++) imp[e] += g_pimp[b*8 + e];
    }
    float z = zs / (float)(NTOK * NE) * 1e-4f;
    float m = 0.f;
#pragma unroll
    for (int e = 0; e < 8; e++) m += imp[e];
    m /= 8.f;
    float v = 0.f;
#pragma unroll
    for (int e = 0; e < 8; e++) { float d = imp[e] - m; v += d*d; }
    v /= 8.f;
    float mm = fmaxf(m, 1e-9f);
    float cvi = v / (mm*mm + 1e-9f);
    float ml = 0.f;
    float ld[8];
#pragma unroll
    for (int e = 0; e < 8; e++) { ld[e] = (float)g_load[e]; ml += ld[e]; }
    ml /= 8.f;
    float vl = 0.f;
#pragma unroll
    for (int e = 0; e < 8; e++) { float d = ld[e] - ml; vl += d*d; }
    vl /= 8.f;
    float mml = fmaxf(ml, 1e-9f);
    float cvl = vl / (mml*mml + 1e-9f);
    out[out_size - 2] = 0.5f * (cvi + cvl);
    out[out_size - 1] = z;
}

// ---------------- launch ----------------
extern "C" void kernel_launch(void* const* d_in, const int* in_sizes, int n_in,
                              void* d_out, int out_size) {
    const float* h   = (const float*)d_in[0];
    const float* Wr  = (const float*)d_in[1];
    const float* br  = (const float*)d_in[2];
    const float* lns = (const float*)d_in[3];
    const float* lnb = (const float*)d_in[4];
    const float* W1  = (const float*)d_in[5];
    const float* b1  = (const float*)d_in[6];
    const float* W2  = (const float*)d_in[7];
    const float* b2  = (const float*)d_in[8];
    float* out = (float*)d_out;

    cudaFuncSetAttribute(k_gemm1, cudaFuncAttributeMaxDynamicSharedMemorySize, SMEM_DYN);
    cudaFuncSetAttribute(k_gemm2, cudaFuncAttributeMaxDynamicSharedMemorySize, SMEM_DYN);

    // lazily created once (first, uncaptured correctness call); reused after.
    static cudaStream_t s_aux = nullptr;
    static cudaEvent_t  ev_fork = nullptr, ev_w = nullptr;
    if (s_aux == nullptr) {
        cudaStreamCreateWithFlags(&s_aux, cudaStreamNonBlocking);
        cudaEventCreateWithFlags(&ev_fork, cudaEventDisableTiming);
        cudaEventCreateWithFlags(&ev_w, cudaEventDisableTiming);
    }

    // fork: weight prep on aux stream, routing chain on main stream
    cudaEventRecord(ev_fork, 0);
    cudaStreamWaitEvent(s_aux, ev_fork, 0);
    k_tw1<<<dim3(2*HH/64, DIM/64, NE), dim3(32, 8), 0, s_aux>>>(W1);
    k_tw2<<<dim3(DIM/64, HH/64, NE), dim3(32, 8), 0, s_aux>>>(W2);
    cudaEventRecord(ev_w, s_aux);

    k_router<<<NTOK/8, 256>>>(h, Wr, br);
    k_assign<<<1, 256>>>();
    k_ln<<<NE*CAP, 256>>>(h, lns, lnb);

    // join: GEMMs need both chains
    cudaStreamWaitEvent(0, ev_w, 0);
    k_gemm1<<<dim3(CAP/128, HH/64, NE), 256, SMEM_DYN>>>(b1);
    k_gemm2<<<dim3(CAP/128, DIM/128, NE), 256, SMEM_DYN>>>(b2);
    k_gather<<<NTOK, 256>>>(out);
    k_loss<<<1, 32>>>(out, out_size);
}

// round 16
// speedup vs baseline: 1.1378x; 1.0102x over previous
#include <cuda_runtime.h>
#include <cuda_fp16.h>
#include <math.h>
#include <stdint.h>

#define NTOK 4096
#define DIM  1024
#define NE   8
#define HH   4096
#define CAP  1280
#define NK   (NTOK*2)

// GEMM tiling (proven): warp 64x32, BK=64, 2-stage; all-fp16 operands
#define BK      64
#define STRD    72
#define TILEB   (128*STRD*2)          // 18432 B
#define STAGEB  (2*TILEB)             // 36864 B
#define SMEM_DYN (2*STAGEB)           // 73728 B

// ---------------- scratch (device globals; no allocations) ----------------
__device__ int   g_e0[NTOK], g_e1[NTOK];
__device__ float g_g0[NTOK], g_g1[NTOK];
__device__ int   g_item_e[NK];
__device__ int   g_item_pos[NK];
__device__ unsigned char g_item_keep[NK];
__device__ float g_item_w[NK];
__device__ int   g_slot_token[NE*CAP];
__device__ int   g_load[NE];
__device__ float g_pimp[512*NE];
__device__ float g_pz[512];

__device__ unsigned short g_xn[(size_t)NE*CAP*DIM];
__device__ unsigned short g_w1[(size_t)NE*2*HH*DIM];
__device__ unsigned short g_w2[(size_t)NE*DIM*HH];
__device__ unsigned short g_v[(size_t)NE*CAP*HH];
__device__ float g_eo[(size_t)NE*CAP*DIM];

// ---------------- helpers ----------------
__device__ __forceinline__ uint32_t smem_u32(const void* p) {
    uint32_t a;
    asm("{ .reg .u64 t; cvta.to.shared.u64 t, %1; cvt.u32.u64 %0, t; }" : "=r"(a) : "l"(p));
    return a;
}
__device__ __forceinline__ void cpa16(uint32_t dst, const void* src) {
    asm volatile("cp.async.ca.shared.global [%0], [%1], 16;" :: "r"(dst), "l"(src));
}
#define CP_COMMIT() asm volatile("cp.async.commit_group;" ::: "memory")
#define CP_WAIT(n)  asm volatile("cp.async.wait_group %0;" :: "n"(n) : "memory")

__device__ __forceinline__ void ldm4(uint32_t* r, uint32_t a) {
    asm volatile("ldmatrix.sync.aligned.m8n8.x4.shared.b16 {%0,%1,%2,%3}, [%4];"
        : "=r"(r[0]), "=r"(r[1]), "=r"(r[2]), "=r"(r[3]) : "r"(a));
}
__device__ __forceinline__ void mma16816(float* d, const uint32_t* a, const uint32_t* b0) {
    asm volatile("mma.sync.aligned.m16n8k16.row.col.f32.f16.f16.f32 "
        "{%0,%1,%2,%3}, {%4,%5,%6,%7}, {%8,%9}, {%0,%1,%2,%3};"
        : "+f"(d[0]), "+f"(d[1]), "+f"(d[2]), "+f"(d[3])
        : "r"(a[0]), "r"(a[1]), "r"(a[2]), "r"(a[3]), "r"(b0[0]), "r"(b0[1]));
}
__device__ __forceinline__ unsigned short f2h(float x) {
    __half hh = __float2half_rn(x);
    return *reinterpret_cast<unsigned short*>(&hh);
}

// ---------------- weight transpose + fp16 ----------------
__global__ void k_tw1(const float* __restrict__ W) {
    __shared__ float tile[64][65];
    int e = blockIdx.z;
    int n0 = blockIdx.x * 64, k0 = blockIdx.y * 64;
    const float* S = W + (size_t)e * DIM * (2*HH);
    int tx = threadIdx.x, ty = threadIdx.y;
#pragma unroll
    for (int i = 0; i < 8; i++) {
        int kl = ty + i*8;
        const float* row = S + (size_t)(k0 + kl) * (2*HH) + n0;
        tile[kl][tx]      = row[tx];
        tile[kl][tx + 32] = row[tx + 32];
    }
    __syncthreads();
    size_t ob = (size_t)e * (2*HH) * DIM;
#pragma unroll
    for (int i = 0; i < 8; i++) {
        int nl = ty + i*8;
        unsigned short h0 = f2h(tile[tx*2][nl]);
        unsigned short h1 = f2h(tile[tx*2 + 1][nl]);
        size_t o = ob + (size_t)(n0 + nl) * DIM + k0;
        ((uint32_t*)(g_w1 + o))[tx] = (uint32_t)h0 | ((uint32_t)h1 << 16);
    }
}
__global__ void k_tw2(const float* __restrict__ W) {
    __shared__ float tile[64][65];
    int e = blockIdx.z;
    int n0 = blockIdx.x * 64, k0 = blockIdx.y * 64;
    const float* S = W + (size_t)e * HH * DIM;
    int tx = threadIdx.x, ty = threadIdx.y;
#pragma unroll
    for (int i = 0; i < 8; i++) {
        int kl = ty + i*8;
        const float* row = S + (size_t)(k0 + kl) * DIM + n0;
        tile[kl][tx]      = row[tx];
        tile[kl][tx + 32] = row[tx + 32];
    }
    __syncthreads();
    size_t ob = (size_t)e * DIM * HH;
#pragma unroll
    for (int i = 0; i < 8; i++) {
        int nl = ty + i*8;
        unsigned short h0 = f2h(tile[tx*2][nl]);
        unsigned short h1 = f2h(tile[tx*2 + 1][nl]);
        size_t o = ob + (size_t)(n0 + nl) * HH + k0;
        ((uint32_t*)(g_w2 + o))[tx] = (uint32_t)h0 | ((uint32_t)h1 << 16);
    }
}

// ---------------- router + fused stats ----------------
__global__ void k_router(const float* __restrict__ x, const float* __restrict__ Wr,
                         const float* __restrict__ br) {
    int warp = threadIdx.x >> 5, lane = threadIdx.x & 31;
    int n = blockIdx.x * 8 + warp;
    float acc[8];
#pragma unroll
    for (int j = 0; j < 8; j++) acc[j] = 0.f;
    const float* xr = x + (size_t)n * DIM;
    for (int d = lane; d < DIM; d += 32) {
        float xv = xr[d];
        float4 w0 = *(const float4*)(Wr + (size_t)d * 8);
        float4 w1 = *(const float4*)(Wr + (size_t)d * 8 + 4);
        acc[0] += xv * w0.x; acc[1] += xv * w0.y; acc[2] += xv * w0.z; acc[3] += xv * w0.w;
        acc[4] += xv * w1.x; acc[5] += xv * w1.y; acc[6] += xv * w1.z; acc[7] += xv * w1.w;
    }
#pragma unroll
    for (int off = 16; off; off >>= 1)
#pragma unroll
        for (int j = 0; j < 8; j++) acc[j] += __shfl_down_sync(0xffffffffu, acc[j], off);
    __shared__ float simp[8][8];
    __shared__ float simz[8];
    if (lane == 0) {
        float lg[8];
#pragma unroll
        for (int j = 0; j < 8; j++) lg[j] = acc[j] + br[j];
        int b0 = 0;
#pragma unroll
        for (int j = 1; j < 8; j++) if (lg[j] > lg[b0]) b0 = j;
        int b1 = (b0 == 0) ? 1 : 0;
#pragma unroll
        for (int j = 0; j < 8; j++) if (j != b0 && lg[j] > lg[b1]) b1 = j;
        g_e0[n] = b0; g_e1[n] = b1;
        float gg = 1.f / (1.f + expf(lg[b1] - lg[b0]));
        g_g0[n] = gg; g_g1[n] = 1.f - gg;
        float m = lg[0];
#pragma unroll
        for (int j = 1; j < 8; j++) m = fmaxf(m, lg[j]);
        float p[8], s = 0.f, zs = 0.f;
#pragma unroll
        for (int j = 0; j < 8; j++) { p[j] = expf(lg[j] - m); s += p[j]; zs += lg[j]*lg[j]; }
#pragma unroll
        for (int j = 0; j < 8; j++) simp[warp][j] = p[j] / s;
        simz[warp] = zs;
    }
    __syncthreads();
    if (threadIdx.x < 8) {
        float tsum = 0.f;
#pragma unroll
        for (int w2 = 0; w2 < 8; w2++) tsum += simp[w2][threadIdx.x];
        g_pimp[blockIdx.x*8 + threadIdx.x] = tsum;
    } else if (threadIdx.x == 8) {
        float tz = 0.f;
#pragma unroll
        for (int w2 = 0; w2 < 8; w2++) tz += simz[w2];
        g_pz[blockIdx.x] = tz;
    }
}

// ---------------- slot assignment (parallel: reg counters + warp scans) -----
__global__ void k_assign() {
    __shared__ int scnt[NE][256];        // expert-major, conflict-free
    int t = threadIdx.x, w = t >> 5, l = t & 31;

    // phase 1: per-thread counts with static-indexed registers
    int its[32];
    int i0 = t * 32;
#pragma unroll
    for (int j = 0; j < 32; j++) {
        int i = i0 + j;
        its[j] = (i < NTOK) ? g_e0[i] : g_e1[i - NTOK];
    }
    int cnt[NE];
#pragma unroll
    for (int e = 0; e < NE; e++) cnt[e] = 0;
#pragma unroll
    for (int j = 0; j < 32; j++)
#pragma unroll
        for (int e = 0; e < NE; e++) cnt[e] += (its[j] == e);
#pragma unroll
    for (int e = 0; e < NE; e++) scnt[e][t] = cnt[e];
    __syncthreads();

    // phase 2: warp w scans expert w over 256 thread-counts (8 chunks of 32)
    {
        int run = 0;
#pragma unroll
        for (int k = 0; k < 8; k++) {
            int vv = scnt[w][k*32 + l];
            int inc = vv;
#pragma unroll
            for (int off = 1; off < 32; off <<= 1) {
                int xs = __shfl_up_sync(0xffffffffu, inc, off);
                if (l >= off) inc += xs;
            }
            scnt[w][k*32 + l] = run + inc - vv;   // exclusive prefix
            run += __shfl_sync(0xffffffffu, inc, 31);
        }
        if (l == 0) g_load[w] = (run < CAP) ? run : CAP;
    }
    __syncthreads();

    // phase 3: assign positions (static-indexed offsets)
    int off[NE];
#pragma unroll
    for (int e = 0; e < NE; e++) off[e] = scnt[e][t];
#pragma unroll
    for (int j = 0; j < 32; j++) {
        int i = i0 + j;
        int nn = (i < NTOK) ? i : (i - NTOK);
        int ex = its[j];
        int pos = 0;
#pragma unroll
        for (int e = 0; e < NE; e++) if (ex == e) pos = off[e]++;
        int keep = (pos < CAP);
        g_item_e[i] = ex;
        g_item_pos[i] = keep ? pos : (CAP - 1);
        g_item_keep[i] = (unsigned char)keep;
        if (keep) g_slot_token[ex*CAP + pos] = nn;
    }
    __syncthreads();

    // phase 4: gate renorm
    for (int n = t; n < NTOK; n += 256) {
        float kg0 = g_item_keep[n]        ? g_g0[n] : 0.f;
        float kg1 = g_item_keep[NTOK + n] ? g_g1[n] : 0.f;
        float denom = fmaxf(kg0 + kg1, 1e-8f);
        g_item_w[n] = kg0 / denom;
        g_item_w[NTOK + n] = kg1 / denom;
    }
}

// ---------------- gather + LayerNorm -> fp16 xn ----------------
__global__ void k_ln(const float* __restrict__ x, const float* __restrict__ lns,
                     const float* __restrict__ lnb) {
    int slot = blockIdx.x;
    int e = slot / CAP, c = slot % CAP;
    if (c >= g_load[e]) return;
    int token = g_slot_token[slot];
    int t = threadIdx.x;
    float4 xv = *(const float4*)(x + (size_t)token*DIM + t*4);
    float s = xv.x + xv.y + xv.z + xv.w;
    float q = xv.x*xv.x + xv.y*xv.y + xv.z*xv.z + xv.w*xv.w;
#pragma unroll
    for (int off = 16; off; off >>= 1) {
        s += __shfl_down_sync(0xffffffffu, s, off);
        q += __shfl_down_sync(0xffffffffu, q, off);
    }
    __shared__ float ws[8], wq[8];
    __shared__ float s_mu, s_rstd;
    int warp = t >> 5, lane = t & 31;
    if (lane == 0) { ws[warp] = s; wq[warp] = q; }
    __syncthreads();
    if (t == 0) {
        float S = 0.f, Q = 0.f;
#pragma unroll
        for (int w = 0; w < 8; w++) { S += ws[w]; Q += wq[w]; }
        float mu = S / DIM;
        float var = Q / DIM - mu*mu;
        s_mu = mu; s_rstd = rsqrtf(var + 1e-5f);
    }
    __syncthreads();
    float mu = s_mu, r = s_rstd;
    float4 sc = *(const float4*)(lns + (size_t)e*DIM + t*4);
    float4 bi = *(const float4*)(lnb + (size_t)e*DIM + t*4);
    unsigned short h[4];
    h[0] = f2h((xv.x - mu)*r*sc.x + bi.x);
    h[1] = f2h((xv.y - mu)*r*sc.y + bi.y);
    h[2] = f2h((xv.z - mu)*r*sc.z + bi.z);
    h[3] = f2h((xv.w - mu)*r*sc.w + bi.w);
    uint2 ph;
    ph.x = (uint32_t)h[0] | ((uint32_t)h[1] << 16);
    ph.y = (uint32_t)h[2] | ((uint32_t)h[3] << 16);
    *(uint2*)(g_xn + (size_t)slot*DIM + t*4) = ph;
}

// =======================================================================
// fp16 warp-MMA core (proven): warp tile 64x32, BK=64, 2-stage.
// =======================================================================
__device__ __forceinline__ void gemm_compute(uint32_t st, int mrow, int ncol,
                                             int lane, float acc[4][4][4]) {
    int aRowL = lane & 15;
    int aCol8 = (lane >> 4) * 8;
    int bRowL = (lane & 7) + ((lane >> 4) & 1) * 8;
    int bCol8 = ((lane >> 3) & 1) * 8;
#pragma unroll
    for (int s = 0; s < 4; s++) {
        uint32_t A[4][4], B[2][4];
#pragma unroll
        for (int m = 0; m < 4; m++) {
            uint32_t off = (uint32_t)((mrow + m*16 + aRowL)*STRD + s*16 + aCol8) * 2;
            ldm4(A[m], st + off);
        }
#pragma unroll
        for (int p = 0; p < 2; p++) {
            uint32_t off = (uint32_t)((ncol + p*16 + bRowL)*STRD + s*16 + bCol8) * 2;
            ldm4(B[p], st + TILEB + off);
        }
#pragma unroll
        for (int m = 0; m < 4; m++)
#pragma unroll
            for (int n = 0; n < 4; n++)
                mma16816(acc[m][n], A[m], &B[n >> 1][(n & 1) * 2]);
    }
}

// ---------------- GEMM1 + register GLU -> v (fp16) ----------------
__global__ void __launch_bounds__(256) k_gemm1(const float* __restrict__ b1) {
    int e  = blockIdx.z;
    int c0 = blockIdx.x * 128;
    if (c0 >= g_load[e]) return;
    int n0 = blockIdx.y * 64;
    extern __shared__ char sm[];
    uint32_t sb = smem_u32(sm);
    int t = threadIdx.x, lane = t & 31, w = t >> 5;
    int mrow = (w & 1) * 64, ncol = (w >> 1) * 32;
    int grp = (w >> 1);

    size_t slotbase = (size_t)e*CAP + c0;
    const unsigned short* A  = g_xn + slotbase*DIM;
    const unsigned short* BG = g_w1 + (size_t)e*2*HH*DIM;

    float acc[4][4][4];
#pragma unroll
    for (int m = 0; m < 4; m++)
#pragma unroll
        for (int n = 0; n < 4; n++)
#pragma unroll
            for (int q = 0; q < 4; q++) acc[m][n][q] = 0.f;

    const int NT = DIM / BK;
    auto load_stage = [&](int kt, int buf) {
        int kb = kt * BK;
        uint32_t st = sb + buf*STAGEB;
        for (int i = t; i < 1024; i += 256) {
            int r = i >> 3, j = i & 7;
            uint32_t d = st + (uint32_t)(r*STRD*2 + j*16);
            cpa16(d, A + (size_t)r*DIM + kb + j*8);
            int g32 = r >> 5, idx = r & 31;
            int col = (idx < 16) ? (n0 + g32*16 + idx)
                                 : (HH + n0 + g32*16 + (idx - 16));
            cpa16(d + TILEB, BG + (size_t)col*DIM + kb + j*8);
        }
    };

    load_stage(0, 0); CP_COMMIT();
    for (int kt = 0; kt < NT; kt++) {
        int buf = kt & 1;
        if (kt + 1 < NT) { load_stage(kt + 1, buf ^ 1); CP_COMMIT(); CP_WAIT(1); }
        else CP_WAIT(0);
        __syncthreads();
        gemm_compute(sb + buf*STAGEB, mrow, ncol, lane, acc);
        __syncthreads();
    }

    int colbase = n0 + grp*16;
    const float* b1a = b1 + (size_t)e*2*HH;
    const float* b1g = b1a + HH;
#pragma unroll
    for (int n = 0; n < 2; n++) {
        int col = colbase + n*8 + (lane & 3)*2;
        float ba0 = b1a[col], ba1 = b1a[col+1];
        float bg0 = b1g[col], bg1 = b1g[col+1];
#pragma unroll
        for (int m = 0; m < 4; m++) {
            int row = mrow + m*16 + (lane >> 2);
            float a0 = acc[m][n][0] + ba0, a1 = acc[m][n][1] + ba1;
            float q0 = acc[m][n+2][0] + bg0, q1 = acc[m][n+2][1] + bg1;
            float v0 = a0 / (1.f + __expf(-q0));
            float v1 = a1 / (1.f + __expf(-q1));
            *(uint32_t*)(g_v + (slotbase + row)*HH + col) =
                (uint32_t)f2h(v0) | ((uint32_t)f2h(v1) << 16);
            a0 = acc[m][n][2] + ba0; a1 = acc[m][n][3] + ba1;
            q0 = acc[m][n+2][2] + bg0; q1 = acc[m][n+2][3] + bg1;
            v0 = a0 / (1.f + __expf(-q0));
            v1 = a1 / (1.f + __expf(-q1));
            *(uint32_t*)(g_v + (slotbase + row + 8)*HH + col) =
                (uint32_t)f2h(v0) | ((uint32_t)f2h(v1) << 16);
        }
    }
}

// ---------------- GEMM2 -> eo (fp32) ----------------
__global__ void __launch_bounds__(256) k_gemm2(const float* __restrict__ b2) {
    int e  = blockIdx.z;
    int c0 = blockIdx.x * 128;
    if (c0 >= g_load[e]) return;
    int n0 = blockIdx.y * 128;
    extern __shared__ char sm[];
    uint32_t sb = smem_u32(sm);
    int t = threadIdx.x, lane = t & 31, w = t >> 5;
    int mrow = (w & 1) * 64, ncol = (w >> 1) * 32;

    size_t slotbase = (size_t)e*CAP + c0;
    const unsigned short* A  = g_v + slotbase*HH;
    const unsigned short* BG = g_w2 + (size_t)e*DIM*HH;

    float acc[4][4][4];
#pragma unroll
    for (int m = 0; m < 4; m++)
#pragma unroll
        for (int n = 0; n < 4; n++)
#pragma unroll
            for (int q = 0; q < 4; q++) acc[m][n][q] = 0.f;

    const int NT = HH / BK;
    auto load_stage = [&](int kt, int buf) {
        int kb = kt * BK;
        uint32_t st = sb + buf*STAGEB;
        for (int i = t; i < 1024; i += 256) {
            int r = i >> 3, j = i & 7;
            uint32_t d = st + (uint32_t)(r*STRD*2 + j*16);
            cpa16(d, A + (size_t)r*HH + kb + j*8);
            int col = n0 + r;
            cpa16(d + TILEB, BG + (size_t)col*HH + kb + j*8);
        }
    };

    load_stage(0, 0); CP_COMMIT();
    for (int kt = 0; kt < NT; kt++) {
        int buf = kt & 1;
        if (kt + 1 < NT) { load_stage(kt + 1, buf ^ 1); CP_COMMIT(); CP_WAIT(1); }
        else CP_WAIT(0);
        __syncthreads();
        gemm_compute(sb + buf*STAGEB, mrow, ncol, lane, acc);
        __syncthreads();
    }

    const float* b2e = b2 + (size_t)e*DIM;
#pragma unroll
    for (int m = 0; m < 4; m++)
#pragma unroll
        for (int n = 0; n < 4; n++) {
            int row = mrow + m*16 + (lane >> 2);
            int col = n0 + ncol + n*8 + (lane & 3)*2;
            float2 v0 = make_float2(acc[m][n][0] + b2e[col], acc[m][n][1] + b2e[col+1]);
            float2 v1 = make_float2(acc[m][n][2] + b2e[col], acc[m][n][3] + b2e[col+1]);
            *(float2*)(g_eo + (slotbase + row)*DIM + col)     = v0;
            *(float2*)(g_eo + (slotbase + row + 8)*DIM + col) = v1;
        }
}

// ---------------- gather + combine -> y ----------------
__global__ void k_gather(float* __restrict__ out) {
    int n = blockIdx.x, t = threadIdx.x;
    int d = t * 4;
    float w0 = g_item_w[n], w1 = g_item_w[NTOK + n];
    float4 acc = make_float4(0.f, 0.f, 0.f, 0.f);
    if (w0 != 0.f) {
        int e = g_item_e[n], p = g_item_pos[n];
        float4 r = *(const float4*)(g_eo + ((size_t)e*CAP + p)*DIM + d);
        acc.x += w0*r.x; acc.y += w0*r.y; acc.z += w0*r.z; acc.w += w0*r.w;
    }
    if (w1 != 0.f) {
        int e = g_item_e[NTOK + n], p = g_item_pos[NTOK + n];
        float4 r = *(const float4*)(g_eo + ((size_t)e*CAP + p)*DIM + d);
        acc.x += w1*r.x; acc.y += w1*r.y; acc.z += w1*r.z; acc.w += w1*r.w;
    }
    *(float4*)(out + (size_t)n*DIM + d) = acc;
}

// ---------------- losses ----------------
__global__ void k_loss(float* __restrict__ out, int out_size) {
    if (threadIdx.x != 0) return;
    float imp[8]; float zs = 0.f;
#pragma unroll
    for (int e = 0; e < 8; e++) imp[e] = 0.f;
    for (int b = 0; b < 512; b++) {
        zs += g_pz[b];
#pragma unroll
        for (int e = 0; e < 8; e++) imp[e] += g_pimp[b*8 + e];
    }
    float z = zs / (float)(NTOK * NE) * 1e-4f;
    float m = 0.f;
#pragma unroll
    for (int e = 0; e < 8; e++) m += imp[e];
    m /= 8.f;
    float v = 0.f;
#pragma unroll
    for (int e = 0; e < 8; e++) { float d = imp[e] - m; v += d*d; }
    v /= 8.f;
    float mm = fmaxf(m, 1e-9f);
    float cvi = v / (mm*mm + 1e-9f);
    float ml = 0.f;
    float ld[8];
#pragma unroll
    for (int e = 0; e < 8; e++) { ld[e] = (float)g_load[e]; ml += ld[e]; }
    ml /= 8.f;
    float vl = 0.f;
#pragma unroll
    for (int e = 0; e < 8; e++) { float d = ld[e] - ml; vl += d*d; }
    vl /= 8.f;
    float mml = fmaxf(ml, 1e-9f);
    float cvl = vl / (mml*mml + 1e-9f);
    out[out_size - 2] = 0.5f * (cvi + cvl);
    out[out_size - 1] = z;
}

// ---------------- launch ----------------
extern "C" void kernel_launch(void* const* d_in, const int* in_sizes, int n_in,
                              void* d_out, int out_size) {
    const float* h   = (const float*)d_in[0];
    const float* Wr  = (const float*)d_in[1];
    const float* br  = (const float*)d_in[2];
    const float* lns = (const float*)d_in[3];
    const float* lnb = (const float*)d_in[4];
    const float* W1  = (const float*)d_in[5];
    const float* b1  = (const float*)d_in[6];
    const float* W2  = (const float*)d_in[7];
    const float* b2  = (const float*)d_in[8];
    float* out = (float*)d_out;

    cudaFuncSetAttribute(k_gemm1, cudaFuncAttributeMaxDynamicSharedMemorySize, SMEM_DYN);
    cudaFuncSetAttribute(k_gemm2, cudaFuncAttributeMaxDynamicSharedMemorySize, SMEM_DYN);

    static cudaStream_t s_aux = nullptr;
    static cudaEvent_t  ev_fork = nullptr, ev_w1 = nullptr, ev_w2 = nullptr;
    if (s_aux == nullptr) {
        cudaStreamCreateWithFlags(&s_aux, cudaStreamNonBlocking);
        cudaEventCreateWithFlags(&ev_fork, cudaEventDisableTiming);
        cudaEventCreateWithFlags(&ev_w1, cudaEventDisableTiming);
        cudaEventCreateWithFlags(&ev_w2, cudaEventDisableTiming);
    }

    // fork: weight prep on aux stream; routing chain on main stream
    cudaEventRecord(ev_fork, 0);
    cudaStreamWaitEvent(s_aux, ev_fork, 0);
    k_tw1<<<dim3(2*HH/64, DIM/64, NE), dim3(32, 8), 0, s_aux>>>(W1);
    cudaEventRecord(ev_w1, s_aux);
    k_tw2<<<dim3(DIM/64, HH/64, NE), dim3(32, 8), 0, s_aux>>>(W2);
    cudaEventRecord(ev_w2, s_aux);

    k_router<<<NTOK/8, 256>>>(h, Wr, br);
    k_assign<<<1, 256>>>();
    k_ln<<<NE*CAP, 256>>>(h, lns, lnb);

    // fine-grained joins: gemm1 needs only w1; gemm2 needs w2 (tw2 overlaps gemm1)
    cudaStreamWaitEvent(0, ev_w1, 0);
    k_gemm1<<<dim3(CAP/128, HH/64, NE), 256, SMEM_DYN>>>(b1);
    cudaStreamWaitEvent(0, ev_w2, 0);
    k_gemm2<<<dim3(CAP/128, DIM/128, NE), 256, SMEM_DYN>>>(b2);
    k_gather<<<NTOK, 256>>>(out);
    k_loss<<<1, 32>>>(out, out_size);
}

// round 17
// speedup vs baseline: 1.1623x; 1.0216x over previous
#include <cuda_runtime.h>
#include <cuda_fp16.h>
#include <math.h>
#include <stdint.h>

#define NTOK 4096
#define DIM  1024
#define NE   8
#define HH   4096
#define CAP  1280
#define NK   (NTOK*2)

// GEMM tiling (proven): warp 64x32, BK=64, 2-stage; all-fp16 operands
#define BK      64
#define STRD    72
#define TILEB   (128*STRD*2)          // 18432 B
#define STAGEB  (2*TILEB)             // 36864 B
#define SMEM_DYN (2*STAGEB)           // 73728 B

// ---------------- scratch (device globals; no allocations) ----------------
__device__ int   g_e0[NTOK], g_e1[NTOK];
__device__ float g_g0[NTOK], g_g1[NTOK];
__device__ int   g_item_e[NK];
__device__ int   g_item_pos[NK];
__device__ unsigned char g_item_keep[NK];
__device__ float g_item_w[NK];
__device__ int   g_slot_token[NE*CAP];
__device__ int   g_load[NE];
__device__ float g_pimp[512*NE];
__device__ float g_pz[512];

__device__ unsigned short g_xn[(size_t)NE*CAP*DIM];
__device__ unsigned short g_w1[(size_t)NE*2*HH*DIM];
__device__ unsigned short g_w2[(size_t)NE*DIM*HH];
__device__ unsigned short g_v[(size_t)NE*CAP*HH];
__device__ float g_eo[(size_t)NE*CAP*DIM];

// ---------------- helpers ----------------
__device__ __forceinline__ uint32_t smem_u32(const void* p) {
    uint32_t a;
    asm("{ .reg .u64 t; cvta.to.shared.u64 t, %1; cvt.u32.u64 %0, t; }" : "=r"(a) : "l"(p));
    return a;
}
__device__ __forceinline__ void cpa16(uint32_t dst, const void* src) {
    asm volatile("cp.async.ca.shared.global [%0], [%1], 16;" :: "r"(dst), "l"(src));
}
#define CP_COMMIT() asm volatile("cp.async.commit_group;" ::: "memory")
#define CP_WAIT(n)  asm volatile("cp.async.wait_group %0;" :: "n"(n) : "memory")

__device__ __forceinline__ void ldm4(uint32_t* r, uint32_t a) {
    asm volatile("ldmatrix.sync.aligned.m8n8.x4.shared.b16 {%0,%1,%2,%3}, [%4];"
        : "=r"(r[0]), "=r"(r[1]), "=r"(r[2]), "=r"(r[3]) : "r"(a));
}
__device__ __forceinline__ void mma16816(float* d, const uint32_t* a, const uint32_t* b0) {
    asm volatile("mma.sync.aligned.m16n8k16.row.col.f32.f16.f16.f32 "
        "{%0,%1,%2,%3}, {%4,%5,%6,%7}, {%8,%9}, {%0,%1,%2,%3};"
        : "+f"(d[0]), "+f"(d[1]), "+f"(d[2]), "+f"(d[3])
        : "r"(a[0]), "r"(a[1]), "r"(a[2]), "r"(a[3]), "r"(b0[0]), "r"(b0[1]));
}
__device__ __forceinline__ unsigned short f2h(float x) {
    __half hh = __float2half_rn(x);
    return *reinterpret_cast<unsigned short*>(&hh);
}

// ---------------- weight transpose + fp16 ----------------
__global__ void k_tw1(const float* __restrict__ W) {
    __shared__ float tile[64][65];
    int e = blockIdx.z;
    int n0 = blockIdx.x * 64, k0 = blockIdx.y * 64;
    const float* S = W + (size_t)e * DIM * (2*HH);
    int tx = threadIdx.x, ty = threadIdx.y;
#pragma unroll
    for (int i = 0; i < 8; i++) {
        int kl = ty + i*8;
        const float* row = S + (size_t)(k0 + kl) * (2*HH) + n0;
        tile[kl][tx]      = row[tx];
        tile[kl][tx + 32] = row[tx + 32];
    }
    __syncthreads();
    size_t ob = (size_t)e * (2*HH) * DIM;
#pragma unroll
    for (int i = 0; i < 8; i++) {
        int nl = ty + i*8;
        unsigned short h0 = f2h(tile[tx*2][nl]);
        unsigned short h1 = f2h(tile[tx*2 + 1][nl]);
        size_t o = ob + (size_t)(n0 + nl) * DIM + k0;
        ((uint32_t*)(g_w1 + o))[tx] = (uint32_t)h0 | ((uint32_t)h1 << 16);
    }
}
__global__ void k_tw2(const float* __restrict__ W) {
    __shared__ float tile[64][65];
    int e = blockIdx.z;
    int n0 = blockIdx.x * 64, k0 = blockIdx.y * 64;
    const float* S = W + (size_t)e * HH * DIM;
    int tx = threadIdx.x, ty = threadIdx.y;
#pragma unroll
    for (int i = 0; i < 8; i++) {
        int kl = ty + i*8;
        const float* row = S + (size_t)(k0 + kl) * DIM + n0;
        tile[kl][tx]      = row[tx];
        tile[kl][tx + 32] = row[tx + 32];
    }
    __syncthreads();
    size_t ob = (size_t)e * DIM * HH;
#pragma unroll
    for (int i = 0; i < 8; i++) {
        int nl = ty + i*8;
        unsigned short h0 = f2h(tile[tx*2][nl]);
        unsigned short h1 = f2h(tile[tx*2 + 1][nl]);
        size_t o = ob + (size_t)(n0 + nl) * HH + k0;
        ((uint32_t*)(g_w2 + o))[tx] = (uint32_t)h0 | ((uint32_t)h1 << 16);
    }
}

// ---------------- router + fused stats ----------------
__global__ void k_router(const float* __restrict__ x, const float* __restrict__ Wr,
                         const float* __restrict__ br) {
    int warp = threadIdx.x >> 5, lane = threadIdx.x & 31;
    int n = blockIdx.x * 8 + warp;
    float acc[8];
#pragma unroll
    for (int j = 0; j < 8; j++) acc[j] = 0.f;
    const float* xr = x + (size_t)n * DIM;
    for (int d = lane; d < DIM; d += 32) {
        float xv = xr[d];
        float4 w0 = *(const float4*)(Wr + (size_t)d * 8);
        float4 w1 = *(const float4*)(Wr + (size_t)d * 8 + 4);
        acc[0] += xv * w0.x; acc[1] += xv * w0.y; acc[2] += xv * w0.z; acc[3] += xv * w0.w;
        acc[4] += xv * w1.x; acc[5] += xv * w1.y; acc[6] += xv * w1.z; acc[7] += xv * w1.w;
    }
#pragma unroll
    for (int off = 16; off; off >>= 1)
#pragma unroll
        for (int j = 0; j < 8; j++) acc[j] += __shfl_down_sync(0xffffffffu, acc[j], off);
    __shared__ float simp[8][8];
    __shared__ float simz[8];
    if (lane == 0) {
        float lg[8];
#pragma unroll
        for (int j = 0; j < 8; j++) lg[j] = acc[j] + br[j];
        int b0 = 0;
#pragma unroll
        for (int j = 1; j < 8; j++) if (lg[j] > lg[b0]) b0 = j;
        int b1 = (b0 == 0) ? 1 : 0;
#pragma unroll
        for (int j = 0; j < 8; j++) if (j != b0 && lg[j] > lg[b1]) b1 = j;
        g_e0[n] = b0; g_e1[n] = b1;
        float gg = 1.f / (1.f + expf(lg[b1] - lg[b0]));
        g_g0[n] = gg; g_g1[n] = 1.f - gg;
        float m = lg[0];
#pragma unroll
        for (int j = 1; j < 8; j++) m = fmaxf(m, lg[j]);
        float p[8], s = 0.f, zs = 0.f;
#pragma unroll
        for (int j = 0; j < 8; j++) { p[j] = expf(lg[j] - m); s += p[j]; zs += lg[j]*lg[j]; }
#pragma unroll
        for (int j = 0; j < 8; j++) simp[warp][j] = p[j] / s;
        simz[warp] = zs;
    }
    __syncthreads();
    if (threadIdx.x < 8) {
        float tsum = 0.f;
#pragma unroll
        for (int w2 = 0; w2 < 8; w2++) tsum += simp[w2][threadIdx.x];
        g_pimp[blockIdx.x*8 + threadIdx.x] = tsum;
    } else if (threadIdx.x == 8) {
        float tz = 0.f;
#pragma unroll
        for (int w2 = 0; w2 < 8; w2++) tz += simz[w2];
        g_pz[blockIdx.x] = tz;
    }
}

// ---------------- slot assignment: 1024 threads, 8 items/thread ------------
__global__ void __launch_bounds__(1024) k_assign() {
    __shared__ int scnt[NE][1024];       // expert-major
    int t = threadIdx.x, w = t >> 5, l = t & 31;

    // phase 1: per-thread counts (8 items, static-indexed regs)
    int its[8];
    int i0 = t * 8;
#pragma unroll
    for (int j = 0; j < 8; j++) {
        int i = i0 + j;
        its[j] = (i < NTOK) ? g_e0[i] : g_e1[i - NTOK];
    }
    int cnt[NE];
#pragma unroll
    for (int e = 0; e < NE; e++) cnt[e] = 0;
#pragma unroll
    for (int j = 0; j < 8; j++)
#pragma unroll
        for (int e = 0; e < NE; e++) cnt[e] += (its[j] == e);
#pragma unroll
    for (int e = 0; e < NE; e++) scnt[e][t] = cnt[e];
    __syncthreads();

    // phase 2: warps 0..7 scan expert w over 1024 chunk-counts (32 chunks of 32)
    if (w < NE) {
        int run = 0;
#pragma unroll
        for (int k = 0; k < 32; k++) {
            int vv = scnt[w][k*32 + l];
            int inc = vv;
#pragma unroll
            for (int off = 1; off < 32; off <<= 1) {
                int xs = __shfl_up_sync(0xffffffffu, inc, off);
                if (l >= off) inc += xs;
            }
            scnt[w][k*32 + l] = run + inc - vv;   // exclusive prefix
            run += __shfl_sync(0xffffffffu, inc, 31);
        }
        if (l == 0) g_load[w] = (run < CAP) ? run : CAP;
    }
    __syncthreads();

    // phase 3: assign positions
    int off[NE];
#pragma unroll
    for (int e = 0; e < NE; e++) off[e] = scnt[e][t];
#pragma unroll
    for (int j = 0; j < 8; j++) {
        int i = i0 + j;
        int nn = (i < NTOK) ? i : (i - NTOK);
        int ex = its[j];
        int pos = 0;
#pragma unroll
        for (int e = 0; e < NE; e++) if (ex == e) pos = off[e]++;
        int keep = (pos < CAP);
        g_item_e[i] = ex;
        g_item_pos[i] = keep ? pos : (CAP - 1);
        g_item_keep[i] = (unsigned char)keep;
        if (keep) g_slot_token[ex*CAP + pos] = nn;
    }
    __syncthreads();

    // phase 4: gate renorm
    for (int n = t; n < NTOK; n += 1024) {
        float kg0 = g_item_keep[n]        ? g_g0[n] : 0.f;
        float kg1 = g_item_keep[NTOK + n] ? g_g1[n] : 0.f;
        float denom = fmaxf(kg0 + kg1, 1e-8f);
        g_item_w[n] = kg0 / denom;
        g_item_w[NTOK + n] = kg1 / denom;
    }
}

// ---------------- gather + LayerNorm -> fp16 xn ----------------
__global__ void k_ln(const float* __restrict__ x, const float* __restrict__ lns,
                     const float* __restrict__ lnb) {
    int slot = blockIdx.x;
    int e = slot / CAP, c = slot % CAP;
    if (c >= g_load[e]) return;
    int token = g_slot_token[slot];
    int t = threadIdx.x;
    float4 xv = *(const float4*)(x + (size_t)token*DIM + t*4);
    float s = xv.x + xv.y + xv.z + xv.w;
    float q = xv.x*xv.x + xv.y*xv.y + xv.z*xv.z + xv.w*xv.w;
#pragma unroll
    for (int off = 16; off; off >>= 1) {
        s += __shfl_down_sync(0xffffffffu, s, off);
        q += __shfl_down_sync(0xffffffffu, q, off);
    }
    __shared__ float ws[8], wq[8];
    __shared__ float s_mu, s_rstd;
    int warp = t >> 5, lane = t & 31;
    if (lane == 0) { ws[warp] = s; wq[warp] = q; }
    __syncthreads();
    if (t == 0) {
        float S = 0.f, Q = 0.f;
#pragma unroll
        for (int w = 0; w < 8; w++) { S += ws[w]; Q += wq[w]; }
        float mu = S / DIM;
        float var = Q / DIM - mu*mu;
        s_mu = mu; s_rstd = rsqrtf(var + 1e-5f);
    }
    __syncthreads();
    float mu = s_mu, r = s_rstd;
    float4 sc = *(const float4*)(lns + (size_t)e*DIM + t*4);
    float4 bi = *(const float4*)(lnb + (size_t)e*DIM + t*4);
    unsigned short h[4];
    h[0] = f2h((xv.x - mu)*r*sc.x + bi.x);
    h[1] = f2h((xv.y - mu)*r*sc.y + bi.y);
    h[2] = f2h((xv.z - mu)*r*sc.z + bi.z);
    h[3] = f2h((xv.w - mu)*r*sc.w + bi.w);
    uint2 ph;
    ph.x = (uint32_t)h[0] | ((uint32_t)h[1] << 16);
    ph.y = (uint32_t)h[2] | ((uint32_t)h[3] << 16);
    *(uint2*)(g_xn + (size_t)slot*DIM + t*4) = ph;
}

// =======================================================================
// fp16 warp-MMA core (proven): warp tile 64x32, BK=64, 2-stage.
// =======================================================================
__device__ __forceinline__ void gemm_compute(uint32_t st, int mrow, int ncol,
                                             int lane, float acc[4][4][4]) {
    int aRowL = lane & 15;
    int aCol8 = (lane >> 4) * 8;
    int bRowL = (lane & 7) + ((lane >> 4) & 1) * 8;
    int bCol8 = ((lane >> 3) & 1) * 8;
#pragma unroll
    for (int s = 0; s < 4; s++) {
        uint32_t A[4][4], B[2][4];
#pragma unroll
        for (int m = 0; m < 4; m++) {
            uint32_t off = (uint32_t)((mrow + m*16 + aRowL)*STRD + s*16 + aCol8) * 2;
            ldm4(A[m], st + off);
        }
#pragma unroll
        for (int p = 0; p < 2; p++) {
            uint32_t off = (uint32_t)((ncol + p*16 + bRowL)*STRD + s*16 + bCol8) * 2;
            ldm4(B[p], st + TILEB + off);
        }
#pragma unroll
        for (int m = 0; m < 4; m++)
#pragma unroll
            for (int n = 0; n < 4; n++)
                mma16816(acc[m][n], A[m], &B[n >> 1][(n & 1) * 2]);
    }
}

// ---------------- GEMM1 + register GLU -> v (fp16) ----------------
__global__ void __launch_bounds__(256) k_gemm1(const float* __restrict__ b1) {
    int e  = blockIdx.z;
    int c0 = blockIdx.x * 128;
    if (c0 >= g_load[e]) return;
    int n0 = blockIdx.y * 64;
    extern __shared__ char sm[];
    uint32_t sb = smem_u32(sm);
    int t = threadIdx.x, lane = t & 31, w = t >> 5;
    int mrow = (w & 1) * 64, ncol = (w >> 1) * 32;
    int grp = (w >> 1);

    size_t slotbase = (size_t)e*CAP + c0;
    const unsigned short* A  = g_xn + slotbase*DIM;
    const unsigned short* BG = g_w1 + (size_t)e*2*HH*DIM;

    float acc[4][4][4];
#pragma unroll
    for (int m = 0; m < 4; m++)
#pragma unroll
        for (int n = 0; n < 4; n++)
#pragma unroll
            for (int q = 0; q < 4; q++) acc[m][n][q] = 0.f;

    const int NT = DIM / BK;
    auto load_stage = [&](int kt, int buf) {
        int kb = kt * BK;
        uint32_t st = sb + buf*STAGEB;
        for (int i = t; i < 1024; i += 256) {
            int r = i >> 3, j = i & 7;
            uint32_t d = st + (uint32_t)(r*STRD*2 + j*16);
            cpa16(d, A + (size_t)r*DIM + kb + j*8);
            int g32 = r >> 5, idx = r & 31;
            int col = (idx < 16) ? (n0 + g32*16 + idx)
                                 : (HH + n0 + g32*16 + (idx - 16));
            cpa16(d + TILEB, BG + (size_t)col*DIM + kb + j*8);
        }
    };

    load_stage(0, 0); CP_COMMIT();
    for (int kt = 0; kt < NT; kt++) {
        int buf = kt & 1;
        if (kt + 1 < NT) { load_stage(kt + 1, buf ^ 1); CP_COMMIT(); CP_WAIT(1); }
        else CP_WAIT(0);
        __syncthreads();
        gemm_compute(sb + buf*STAGEB, mrow, ncol, lane, acc);
        __syncthreads();
    }

    int colbase = n0 + grp*16;
    const float* b1a = b1 + (size_t)e*2*HH;
    const float* b1g = b1a + HH;
#pragma unroll
    for (int n = 0; n < 2; n++) {
        int col = colbase + n*8 + (lane & 3)*2;
        float ba0 = b1a[col], ba1 = b1a[col+1];
        float bg0 = b1g[col], bg1 = b1g[col+1];
#pragma unroll
        for (int m = 0; m < 4; m++) {
            int row = mrow + m*16 + (lane >> 2);
            float a0 = acc[m][n][0] + ba0, a1 = acc[m][n][1] + ba1;
            float q0 = acc[m][n+2][0] + bg0, q1 = acc[m][n+2][1] + bg1;
            float v0 = a0 / (1.f + __expf(-q0));
            float v1 = a1 / (1.f + __expf(-q1));
            *(uint32_t*)(g_v + (slotbase + row)*HH + col) =
                (uint32_t)f2h(v0) | ((uint32_t)f2h(v1) << 16);
            a0 = acc[m][n][2] + ba0; a1 = acc[m][n][3] + ba1;
            q0 = acc[m][n+2][2] + bg0; q1 = acc[m][n+2][3] + bg1;
            v0 = a0 / (1.f + __expf(-q0));
            v1 = a1 / (1.f + __expf(-q1));
            *(uint32_t*)(g_v + (slotbase + row + 8)*HH + col) =
                (uint32_t)f2h(v0) | ((uint32_t)f2h(v1) << 16);
        }
    }
}

// ---------------- GEMM2 -> eo (fp32) ----------------
__global__ void __launch_bounds__(256) k_gemm2(const float* __restrict__ b2) {
    int e  = blockIdx.z;
    int c0 = blockIdx.x * 128;
    if (c0 >= g_load[e]) return;
    int n0 = blockIdx.y * 128;
    extern __shared__ char sm[];
    uint32_t sb = smem_u32(sm);
    int t = threadIdx.x, lane = t & 31, w = t >> 5;
    int mrow = (w & 1) * 64, ncol = (w >> 1) * 32;

    size_t slotbase = (size_t)e*CAP + c0;
    const unsigned short* A  = g_v + slotbase*HH;
    const unsigned short* BG = g_w2 + (size_t)e*DIM*HH;

    float acc[4][4][4];
#pragma unroll
    for (int m = 0; m < 4; m++)
#pragma unroll
        for (int n = 0; n < 4; n++)
#pragma unroll
            for (int q = 0; q < 4; q++) acc[m][n][q] = 0.f;

    const int NT = HH / BK;
    auto load_stage = [&](int kt, int buf) {
        int kb = kt * BK;
        uint32_t st = sb + buf*STAGEB;
        for (int i = t; i < 1024; i += 256) {
            int r = i >> 3, j = i & 7;
            uint32_t d = st + (uint32_t)(r*STRD*2 + j*16);
            cpa16(d, A + (size_t)r*HH + kb + j*8);
            int col = n0 + r;
            cpa16(d + TILEB, BG + (size_t)col*HH + kb + j*8);
        }
    };

    load_stage(0, 0); CP_COMMIT();
    for (int kt = 0; kt < NT; kt++) {
        int buf = kt & 1;
        if (kt + 1 < NT) { load_stage(kt + 1, buf ^ 1); CP_COMMIT(); CP_WAIT(1); }
        else CP_WAIT(0);
        __syncthreads();
        gemm_compute(sb + buf*STAGEB, mrow, ncol, lane, acc);
        __syncthreads();
    }

    const float* b2e = b2 + (size_t)e*DIM;
#pragma unroll
    for (int m = 0; m < 4; m++)
#pragma unroll
        for (int n = 0; n < 4; n++) {
            int row = mrow + m*16 + (lane >> 2);
            int col = n0 + ncol + n*8 + (lane & 3)*2;
            float2 v0 = make_float2(acc[m][n][0] + b2e[col], acc[m][n][1] + b2e[col+1]);
            float2 v1 = make_float2(acc[m][n][2] + b2e[col], acc[m][n][3] + b2e[col+1]);
            *(float2*)(g_eo + (slotbase + row)*DIM + col)     = v0;
            *(float2*)(g_eo + (slotbase + row + 8)*DIM + col) = v1;
        }
}

// ---------------- gather + combine -> y ----------------
__global__ void k_gather(float* __restrict__ out) {
    int n = blockIdx.x, t = threadIdx.x;
    int d = t * 4;
    float w0 = g_item_w[n], w1 = g_item_w[NTOK + n];
    float4 acc = make_float4(0.f, 0.f, 0.f, 0.f);
    if (w0 != 0.f) {
        int e = g_item_e[n], p = g_item_pos[n];
        float4 r = *(const float4*)(g_eo + ((size_t)e*CAP + p)*DIM + d);
        acc.x += w0*r.x; acc.y += w0*r.y; acc.z += w0*r.z; acc.w += w0*r.w;
    }
    if (w1 != 0.f) {
        int e = g_item_e[NTOK + n], p = g_item_pos[NTOK + n];
        float4 r = *(const float4*)(g_eo + ((size_t)e*CAP + p)*DIM + d);
        acc.x += w1*r.x; acc.y += w1*r.y; acc.z += w1*r.z; acc.w += w1*r.w;
    }
    *(float4*)(out + (size_t)n*DIM + d) = acc;
}

// ---------------- losses ----------------
__global__ void k_loss(float* __restrict__ out, int out_size) {
    if (threadIdx.x != 0) return;
    float imp[8]; float zs = 0.f;
#pragma unroll
    for (int e = 0; e < 8; e++) imp[e] = 0.f;
    for (int b = 0; b < 512; b++) {
        zs += g_pz[b];
#pragma unroll
        for (int e = 0; e < 8; e++) imp[e] += g_pimp[b*8 + e];
    }
    float z = zs / (float)(NTOK * NE) * 1e-4f;
    float m = 0.f;
#pragma unroll
    for (int e = 0; e < 8; e++) m += imp[e];
    m /= 8.f;
    float v = 0.f;
#pragma unroll
    for (int e = 0; e < 8; e++) { float d = imp[e] - m; v += d*d; }
    v /= 8.f;
    float mm = fmaxf(m, 1e-9f);
    float cvi = v / (mm*mm + 1e-9f);
    float ml = 0.f;
    float ld[8];
#pragma unroll
    for (int e = 0; e < 8; e++) { ld[e] = (float)g_load[e]; ml += ld[e]; }
    ml /= 8.f;
    float vl = 0.f;
#pragma unroll
    for (int e = 0; e < 8; e++) { float d = ld[e] - ml; vl += d*d; }
    vl /= 8.f;
    float mml = fmaxf(ml, 1e-9f);
    float cvl = vl / (mml*mml + 1e-9f);
    out[out_size - 2] = 0.5f * (cvi + cvl);
    out[out_size - 1] = z;
}

// ---------------- launch ----------------
extern "C" void kernel_launch(void* const* d_in, const int* in_sizes, int n_in,
                              void* d_out, int out_size) {
    const float* h   = (const float*)d_in[0];
    const float* Wr  = (const float*)d_in[1];
    const float* br  = (const float*)d_in[2];
    const float* lns = (const float*)d_in[3];
    const float* lnb = (const float*)d_in[4];
    const float* W1  = (const float*)d_in[5];
    const float* b1  = (const float*)d_in[6];
    const float* W2  = (const float*)d_in[7];
    const float* b2  = (const float*)d_in[8];
    float* out = (float*)d_out;

    cudaFuncSetAttribute(k_gemm1, cudaFuncAttributeMaxDynamicSharedMemorySize, SMEM_DYN);
    cudaFuncSetAttribute(k_gemm2, cudaFuncAttributeMaxDynamicSharedMemorySize, SMEM_DYN);

    static cudaStream_t s_aux = nullptr;
    static cudaEvent_t  ev_fork = nullptr, ev_w1 = nullptr, ev_w2 = nullptr;
    if (s_aux == nullptr) {
        cudaStreamCreateWithFlags(&s_aux, cudaStreamNonBlocking);
        cudaEventCreateWithFlags(&ev_fork, cudaEventDisableTiming);
        cudaEventCreateWithFlags(&ev_w1, cudaEventDisableTiming);
        cudaEventCreateWithFlags(&ev_w2, cudaEventDisableTiming);
    }

    // fork: weight prep on aux stream; routing chain on main stream
    cudaEventRecord(ev_fork, 0);
    cudaStreamWaitEvent(s_aux, ev_fork, 0);
    k_tw1<<<dim3(2*HH/64, DIM/64, NE), dim3(32, 8), 0, s_aux>>>(W1);
    cudaEventRecord(ev_w1, s_aux);
    k_tw2<<<dim3(DIM/64, HH/64, NE), dim3(32, 8), 0, s_aux>>>(W2);
    cudaEventRecord(ev_w2, s_aux);

    k_router<<<NTOK/8, 256>>>(h, Wr, br);
    k_assign<<<1, 1024>>>();
    k_ln<<<NE*CAP, 256>>>(h, lns, lnb);

    // fine-grained joins: gemm1 needs only w1; gemm2 needs w2 (tw2 overlaps gemm1)
    cudaStreamWaitEvent(0, ev_w1, 0);
    k_gemm1<<<dim3(CAP/128, HH/64, NE), 256, SMEM_DYN>>>(b1);
    cudaStreamWaitEvent(0, ev_w2, 0);
    k_gemm2<<<dim3(CAP/128, DIM/128, NE), 256, SMEM_DYN>>>(b2);
    k_gather<<<NTOK, 256>>>(out);
    k_loss<<<1, 32>>>(out, out_size);
}